// round 6
// baseline (speedup 1.0000x reference)
#include <cuda_runtime.h>
#include <cuda_bf16.h>
#include <cstdint>

#define WDIM 256

// ---------------------------------------------------------------------------
// Scratch (device globals)
// ---------------------------------------------------------------------------
__device__ float g_xs[2560000];            // [N,256]
__device__ float g_xt[2560000];
__device__ unsigned short g_wp_hi[65536];  // W_post bf16 hi [n,k]
__device__ unsigned short g_wp_lo[65536];
// gate/val weights pre-arranged as m16n8k16 B-fragments:
// index = (((c*4 + role)*32 + lane)*32 + slot), role = hl*2+nh = wid&3
// slot: 0-7 = Wg hi [ks*4 + r], 8-15 Wg lo, 16-23 Wv hi, 24-31 Wv lo
__device__ unsigned g_wgv_frag[16384];

typedef unsigned long long u64;

__device__ __forceinline__ void lds_v2u64(u64 &lo, u64 &hi, unsigned addr) {
    asm volatile("ld.shared.v2.u64 {%0,%1}, [%2];" : "=l"(lo), "=l"(hi) : "r"(addr));
}
__device__ __forceinline__ u64 ffma2(u64 a, u64 b, u64 c) {
    u64 d;
    asm("fma.rn.f32x2 %0, %1, %2, %3;" : "=l"(d) : "l"(a), "l"(b), "l"(c));
    return d;
}
__device__ __forceinline__ float unpack_sum(u64 p) {
    unsigned lo, hi;
    asm("mov.b64 {%0,%1}, %2;" : "=r"(lo), "=r"(hi) : "l"(p));
    return __uint_as_float(lo) + __uint_as_float(hi);
}
__device__ __forceinline__ unsigned sw128(unsigned x) { return x ^ ((x >> 3) & 0x70u); }
__device__ __forceinline__ void cpa16(unsigned dst, const void* src) {
    asm volatile("cp.async.cg.shared.global [%0], [%1], 16;" :: "r"(dst), "l"(src));
}
__device__ __forceinline__ void ldm_x4(unsigned* r, unsigned addr) {
    asm volatile("ldmatrix.sync.aligned.m8n8.x4.shared.b16 {%0,%1,%2,%3}, [%4];"
                 : "=r"(r[0]), "=r"(r[1]), "=r"(r[2]), "=r"(r[3]) : "r"(addr));
}
__device__ __forceinline__ void mma16816(float* d, const unsigned* a,
                                         unsigned b0, unsigned b1) {
    asm volatile(
        "mma.sync.aligned.m16n8k16.row.col.f32.bf16.bf16.f32 "
        "{%0,%1,%2,%3}, {%4,%5,%6,%7}, {%8,%9}, {%0,%1,%2,%3};"
        : "+f"(d[0]), "+f"(d[1]), "+f"(d[2]), "+f"(d[3])
        : "r"(a[0]), "r"(a[1]), "r"(a[2]), "r"(a[3]), "r"(b0), "r"(b1));
}
// pack 2 fp32 -> bf16x2 (hi16 = a1, lo16 = a0)
__device__ __forceinline__ unsigned bf2(float a1, float a0) {
    unsigned d;
    asm("cvt.rn.bf16x2.f32 %0, %1, %2;" : "=r"(d) : "f"(a1), "f"(a0));
    return d;
}

// ---------------------------------------------------------------------------
// K1: node GEMM (fp32 FFMA2) — unchanged
// ---------------------------------------------------------------------------
extern "C" __global__ void __launch_bounds__(512, 1)
node_gemm_kernel(const float* __restrict__ x,
                 const float* __restrict__ Wsrc,
                 const float* __restrict__ Wtgt, int N)
{
    extern __shared__ float sm[];
    float4* a4 = reinterpret_cast<float4*>(sm);
    float4* w4 = reinterpret_cast<float4*>(sm + 16640);
    const float* Wm = blockIdx.y ? Wtgt : Wsrc;
    float* og = blockIdx.y ? g_xt : g_xs;

    const int t  = threadIdx.x;
    const int nb = blockIdx.x * 64;

#pragma unroll
    for (int r = 0; r < 8; r++) {
        int id = t + 512 * r;
        int row = id >> 6, c4 = id & 63;
        int n = nb + row;
        float4 v = make_float4(0.f, 0.f, 0.f, 0.f);
        if (n < N) v = __ldg(reinterpret_cast<const float4*>(x + (size_t)n * WDIM) + c4);
        a4[row * 65 + c4] = v;
    }

    const int et = t >> 5, jt = t & 31;
    unsigned sa = (unsigned)__cvta_generic_to_shared(sm);
    unsigned sw = sa + 16640u * 4u;

    u64 accp[4][8];
#pragma unroll
    for (int ee = 0; ee < 4; ee++)
#pragma unroll
        for (int jj = 0; jj < 8; jj++) accp[ee][jj] = 0ull;

#pragma unroll 1
    for (int kt = 0; kt < 8; kt++) {
        __syncthreads();
#pragma unroll
        for (int r = 0; r < 4; r++) {
            int id = t + 512 * r;
            int j = id >> 3, kq = id & 7;
            w4[j * 8 + (kq ^ ((j >> 3) & 7))] =
                __ldg(reinterpret_cast<const float4*>(Wm + (size_t)j * WDIM + kt * 32) + kq);
        }
        __syncthreads();
#pragma unroll
        for (int kq = 0; kq < 8; kq++) {
            u64 aL[4], aH[4];
#pragma unroll
            for (int ee = 0; ee < 4; ee++)
                lds_v2u64(aL[ee], aH[ee],
                          sa + (unsigned)(((et * 4 + ee) * 65 + kt * 8 + kq) * 16));
#pragma unroll
            for (int half = 0; half < 2; half++) {
                u64 bL[4], bH[4];
#pragma unroll
                for (int jj = 0; jj < 4; jj++)
                    lds_v2u64(bL[jj], bH[jj],
                              sw + (unsigned)(((jt * 8 + half * 4 + jj) * 8 + (kq ^ (jt & 7))) * 16));
#pragma unroll
                for (int ee = 0; ee < 4; ee++)
#pragma unroll
                    for (int jj = 0; jj < 4; jj++)
                        accp[ee][half * 4 + jj] =
                            ffma2(aH[ee], bH[jj], ffma2(aL[ee], bL[jj], accp[ee][half * 4 + jj]));
            }
        }
    }

#pragma unroll
    for (int ee = 0; ee < 4; ee++) {
        int n = nb + et * 4 + ee;
        if (n >= N) continue;
        float r0 = unpack_sum(accp[ee][0]), r1 = unpack_sum(accp[ee][1]);
        float r2 = unpack_sum(accp[ee][2]), r3 = unpack_sum(accp[ee][3]);
        float r4 = unpack_sum(accp[ee][4]), r5 = unpack_sum(accp[ee][5]);
        float r6 = unpack_sum(accp[ee][6]), r7 = unpack_sum(accp[ee][7]);
        float4* py = reinterpret_cast<float4*>(og + (size_t)n * WDIM + jt * 8);
        py[0] = make_float4(r0, r1, r2, r3);
        py[1] = make_float4(r4, r5, r6, r7);
    }
}

// ---------------------------------------------------------------------------
// Weight preprocessing: W_post hi/lo split + Wg/Wv B-fragment pre-arrangement
// ---------------------------------------------------------------------------
extern "C" __global__ void wsplit_kernel(const float* __restrict__ Wp,
                                         const float* __restrict__ Wg,
                                         const float* __restrict__ Wv)
{
    int i = blockIdx.x * blockDim.x + threadIdx.x;
    if (i < 65536) {
        float v = Wp[i];
        __nv_bfloat16 h = __float2bfloat16(v);
        float lof = v - __bfloat162float(h);
        __nv_bfloat16 l = __float2bfloat16(lof);
        g_wp_hi[i] = *reinterpret_cast<unsigned short*>(&h);
        g_wp_lo[i] = *reinterpret_cast<unsigned short*>(&l);
    }
    if (i < 16384) {
        // decode fragment coordinates (must mirror P2 consumption exactly)
        int c    = i >> 12;
        int role = (i >> 10) & 3;        // hl*2 + nh
        int hl   = role >> 1, nh = role & 1;
        int lane = (i >> 5) & 31;
        int slot = i & 31;
        int m  = slot >> 3;              // 0 gh, 1 gl, 2 vh, 3 vl
        int r8 = slot & 7;
        int ks = r8 >> 2;
        int r  = r8 & 3;
        int j  = r >> 1, p = r & 1;
        int h = c * 2 + hl;
        int f = nh * 16 + j * 8 + (lane >> 2);
        int d = ks * 16 + p * 8 + 2 * (lane & 3);
        const float* Wm = (m < 2) ? Wg : Wv;
        float v0 = Wm[(size_t)h * 1024 + f * 32 + d];
        float v1 = Wm[(size_t)h * 1024 + f * 32 + d + 1];
        if ((m & 1) == 0) {
            g_wgv_frag[i] = bf2(v1, v0);
        } else {
            float h0 = __bfloat162float(__float2bfloat16(v0));
            float h1 = __bfloat162float(__float2bfloat16(v1));
            g_wgv_frag[i] = bf2(v1 - h1, v0 - h0);
        }
    }
}

// ---------------------------------------------------------------------------
// K2 (fused), R6: double-buffered W_post stage + register-direct gate/val
// fragments + 3 syncs/chunk.
// smem (bytes): tgt@0(pad to 1024) | XNH@1024 XNL@9216 GINH@17408 GINL@25600
//   | ACTH@33792 ACTL@41984 | WP buf0@50176 (hi 32K + lo 32K) buf1@115712
//   total 181248
// ---------------------------------------------------------------------------
#define XNH_O  1024u
#define XNL_O  9216u
#define GINH_O 17408u
#define GINL_O 25600u
#define ACTH_O 33792u
#define ACTL_O 41984u
#define WP_O   50176u
#define WPBUF  65536u

extern "C" __global__ void __launch_bounds__(512, 1)
fused_edge_kernel(const int* __restrict__ eidx, const int* __restrict__ eattr,
                  const float* __restrict__ emb, float* __restrict__ out, int E)
{
    extern __shared__ char smc[];
    unsigned sb = (unsigned)__cvta_generic_to_shared(smc);
    int* tgt_s = reinterpret_cast<int*>(smc);
    const int t = threadIdx.x, lane = t & 31, wid = t >> 5;
    const int eb = blockIdx.x * 64;

    if (t < 64) {
        int e = eb + t;
        tgt_s[t] = (e < E) ? __ldg(eidx + E + e) : -1;
    }
    __syncthreads();

    // W_post warp tile 32x32: 16 warps = 2m x 8n
    const int wm = wid & 1, wn = wid >> 1;
    const int m0 = wm * 32, n0 = wn * 32;
    float acc[2][4][4];
#pragma unroll
    for (int mt = 0; mt < 2; mt++)
#pragma unroll
        for (int nn = 0; nn < 4; nn++)
#pragma unroll
            for (int q = 0; q < 4; q++) acc[mt][nn][q] = 0.f;

    const int e_l = t >> 3, sub = t & 7;
    const int e = eb + e_l;
    const int eg = wid >> 2, hl = (wid >> 1) & 1, nh = wid & 1;
    const int role = wid & 3;

    // ---- stage W_post chunk cc into buffer cc&1 ----
    auto stage_wp = [&](int cc) {
        unsigned base = sb + WP_O + (unsigned)(cc & 1) * WPBUF;
#pragma unroll
        for (int i = 0; i < 4; i++) {
            int u = t + 512 * i;
            int n = u >> 3, q = u & 7;
            unsigned off = sw128((unsigned)(n * 128 + q * 16));
            cpa16(base + off,           g_wp_hi + (size_t)n * 256 + cc * 64 + q * 8);
            cpa16(base + 32768u + off,  g_wp_lo + (size_t)n * 256 + cc * 64 + q * 8);
        }
        asm volatile("cp.async.commit_group;" ::: "memory");
    };

    stage_wp(0);

#pragma unroll 1
    for (int c = 0; c < 4; c++) {
        if (c < 3) stage_wp(c + 1);

        // ---- P1: xn/gin for this chunk's 2 heads ----
        {
            unsigned soff = sw128((unsigned)(e_l * 128 + sub * 16));
            if (e < E) {
                int s  = __ldg(eidx + e);
                int tg = tgt_s[e_l];
                const float4* ps = reinterpret_cast<const float4*>(
                    g_xs + (size_t)s * WDIM + c * 64 + sub * 8);
                const float4* pt = reinterpret_cast<const float4*>(
                    g_xt + (size_t)tg * WDIM + c * 64 + sub * 8);
                float xx[8];
                float4 a0 = ps[0], a1 = ps[1], b0 = pt[0], b1 = pt[1];
                xx[0] = a0.x + b0.x; xx[1] = a0.y + b0.y; xx[2] = a0.z + b0.z; xx[3] = a0.w + b0.w;
                xx[4] = a1.x + b1.x; xx[5] = a1.y + b1.y; xx[6] = a1.z + b1.z; xx[7] = a1.w + b1.w;
                float sum = 0.f, sq = 0.f;
#pragma unroll
                for (int i = 0; i < 8; i++) { sum += xx[i]; sq += xx[i] * xx[i]; }
                sum += __shfl_xor_sync(0xFFFFFFFFu, sum, 1);
                sq  += __shfl_xor_sync(0xFFFFFFFFu, sq, 1);
                sum += __shfl_xor_sync(0xFFFFFFFFu, sum, 2);
                sq  += __shfl_xor_sync(0xFFFFFFFFu, sq, 2);
                float mu = sum * (1.f / 32.f);
                float var = sq * (1.f / 32.f) - mu * mu;
                float rstd = rsqrtf(var + 1e-5f);

                float bag[8];
#pragma unroll
                for (int i = 0; i < 8; i++) bag[i] = 0.f;
                float cnt = 0.f;
#pragma unroll
                for (int b = 0; b < 3; b++) {
                    int a = __ldg(eattr + (size_t)e * 3 + b);
                    if (a != 0) {
                        cnt += 1.f;
                        const float4* pe = reinterpret_cast<const float4*>(
                            emb + (size_t)a * WDIM + c * 64 + sub * 8);
                        float4 e0 = __ldg(pe), e1 = __ldg(pe + 1);
                        bag[0] += e0.x; bag[1] += e0.y; bag[2] += e0.z; bag[3] += e0.w;
                        bag[4] += e1.x; bag[5] += e1.y; bag[6] += e1.z; bag[7] += e1.w;
                    }
                }
                float inv = 1.f / fmaxf(cnt, 1.f);
                float xn[8], gn[8];
#pragma unroll
                for (int i = 0; i < 8; i++) {
                    xn[i] = (xx[i] - mu) * rstd;
                    gn[i] = xn[i] + bag[i] * inv;
                }
                unsigned xh[4], xl[4], gh[4], gl[4];
#pragma unroll
                for (int p = 0; p < 4; p++) {
                    unsigned hp = bf2(xn[2 * p + 1], xn[2 * p]);
                    float h0 = __uint_as_float(hp << 16);
                    float h1 = __uint_as_float(hp & 0xFFFF0000u);
                    xh[p] = hp;
                    xl[p] = bf2(xn[2 * p + 1] - h1, xn[2 * p] - h0);
                    hp = bf2(gn[2 * p + 1], gn[2 * p]);
                    h0 = __uint_as_float(hp << 16);
                    h1 = __uint_as_float(hp & 0xFFFF0000u);
                    gh[p] = hp;
                    gl[p] = bf2(gn[2 * p + 1] - h1, gn[2 * p] - h0);
                }
                asm volatile("st.shared.v4.b32 [%0], {%1,%2,%3,%4};" ::
                             "r"(sb + XNH_O + soff), "r"(xh[0]), "r"(xh[1]), "r"(xh[2]), "r"(xh[3]));
                asm volatile("st.shared.v4.b32 [%0], {%1,%2,%3,%4};" ::
                             "r"(sb + XNL_O + soff), "r"(xl[0]), "r"(xl[1]), "r"(xl[2]), "r"(xl[3]));
                asm volatile("st.shared.v4.b32 [%0], {%1,%2,%3,%4};" ::
                             "r"(sb + GINH_O + soff), "r"(gh[0]), "r"(gh[1]), "r"(gh[2]), "r"(gh[3]));
                asm volatile("st.shared.v4.b32 [%0], {%1,%2,%3,%4};" ::
                             "r"(sb + GINL_O + soff), "r"(gl[0]), "r"(gl[1]), "r"(gl[2]), "r"(gl[3]));
            } else {
                asm volatile("st.shared.v4.b32 [%0], {%1,%1,%1,%1};" :: "r"(sb + XNH_O + soff), "r"(0u));
                asm volatile("st.shared.v4.b32 [%0], {%1,%1,%1,%1};" :: "r"(sb + XNL_O + soff), "r"(0u));
                asm volatile("st.shared.v4.b32 [%0], {%1,%1,%1,%1};" :: "r"(sb + GINH_O + soff), "r"(0u));
                asm volatile("st.shared.v4.b32 [%0], {%1,%1,%1,%1};" :: "r"(sb + GINL_O + soff), "r"(0u));
            }
        }
        __syncthreads();   // S1: xn/gin visible

        // ---- P2: gate/val HMMA, B-fragments via direct LDG ----
        {
            unsigned u[32];
            const uint4* pw = reinterpret_cast<const uint4*>(
                g_wgv_frag + ((size_t)((c * 4 + role) * 32 + lane) * 32));
#pragma unroll
            for (int i = 0; i < 8; i++) {
                uint4 q = __ldg(pw + i);
                u[i * 4] = q.x; u[i * 4 + 1] = q.y; u[i * 4 + 2] = q.z; u[i * 4 + 3] = q.w;
            }
            unsigned agh[2][4], agl[2][4], axh[2][4], axl[2][4];
            unsigned arow = (unsigned)((eg * 16 + (lane & 15)) * 128 + hl * 64 + (lane >> 4) * 16);
#pragma unroll
            for (int ks = 0; ks < 2; ks++) {
                unsigned off = sw128(arow + ks * 32);
                ldm_x4(agh[ks], sb + GINH_O + off);
                ldm_x4(agl[ks], sb + GINL_O + off);
                ldm_x4(axh[ks], sb + XNH_O + off);
                ldm_x4(axl[ks], sb + XNL_O + off);
            }
            float gacc[2][4], vacc[2][4];
#pragma unroll
            for (int j = 0; j < 2; j++)
#pragma unroll
                for (int q = 0; q < 4; q++) { gacc[j][q] = 0.f; vacc[j][q] = 0.f; }
#pragma unroll
            for (int ks = 0; ks < 2; ks++)
#pragma unroll
                for (int j = 0; j < 2; j++) {
                    mma16816(gacc[j], agh[ks], u[ks * 4 + 2 * j],      u[ks * 4 + 2 * j + 1]);
                    mma16816(gacc[j], agh[ks], u[8 + ks * 4 + 2 * j],  u[8 + ks * 4 + 2 * j + 1]);
                    mma16816(gacc[j], agl[ks], u[ks * 4 + 2 * j],      u[ks * 4 + 2 * j + 1]);
                    mma16816(vacc[j], axh[ks], u[16 + ks * 4 + 2 * j], u[16 + ks * 4 + 2 * j + 1]);
                    mma16816(vacc[j], axh[ks], u[24 + ks * 4 + 2 * j], u[24 + ks * 4 + 2 * j + 1]);
                    mma16816(vacc[j], axl[ks], u[16 + ks * 4 + 2 * j], u[16 + ks * 4 + 2 * j + 1]);
                }
#pragma unroll
            for (int j = 0; j < 2; j++)
#pragma unroll
                for (int half = 0; half < 2; half++) {
                    float a0 = fmaxf(gacc[j][half * 2], 0.f) * vacc[j][half * 2];
                    float a1 = fmaxf(gacc[j][half * 2 + 1], 0.f) * vacc[j][half * 2 + 1];
                    int row = eg * 16 + (lane >> 2) + half * 8;
                    int col = hl * 32 + nh * 16 + j * 8 + (lane & 3) * 2;
                    unsigned off = sw128((unsigned)(row * 128 + col * 2));
                    unsigned hp = bf2(a1, a0);
                    float h0 = __uint_as_float(hp << 16);
                    float h1 = __uint_as_float(hp & 0xFFFF0000u);
                    unsigned lp = bf2(a1 - h1, a0 - h0);
                    asm volatile("st.shared.b32 [%0], %1;" :: "r"(sb + ACTH_O + off), "r"(hp));
                    asm volatile("st.shared.b32 [%0], %1;" :: "r"(sb + ACTL_O + off), "r"(lp));
                }
        }
        if (c < 3) {
            asm volatile("cp.async.wait_group 1;" ::: "memory");
        } else {
            asm volatile("cp.async.wait_group 0;" ::: "memory");
        }
        __syncthreads();   // S2: act visible + WP(c) staged for all threads

        // ---- P3: W_post chunk mainloop ----
        {
            unsigned wpb = sb + WP_O + (unsigned)(c & 1) * WPBUF;
#pragma unroll
            for (int ks = 0; ks < 4; ks++) {
                unsigned ah[2][4], al[2][4];
#pragma unroll
                for (int mt = 0; mt < 2; mt++) {
                    unsigned off = sw128((unsigned)((m0 + mt * 16 + (lane & 15)) * 128
                                                    + ks * 32 + (lane >> 4) * 16));
                    ldm_x4(ah[mt], sb + ACTH_O + off);
                    ldm_x4(al[mt], sb + ACTL_O + off);
                }
#pragma unroll
                for (int nt = 0; nt < 2; nt++) {
                    unsigned off = sw128((unsigned)((n0 + nt * 16 + (lane & 7)
                                                     + ((lane >> 4) & 1) * 8) * 128
                                                    + ks * 32 + ((lane >> 3) & 1) * 16));
                    unsigned bh[4], bl[4];
                    ldm_x4(bh, wpb + off);
                    ldm_x4(bl, wpb + 32768u + off);
#pragma unroll
                    for (int j = 0; j < 2; j++) {
                        int nn = nt * 2 + j;
#pragma unroll
                        for (int mt = 0; mt < 2; mt++) {
                            mma16816(acc[mt][nn], ah[mt], bh[2 * j], bh[2 * j + 1]);
                            mma16816(acc[mt][nn], ah[mt], bl[2 * j], bl[2 * j + 1]);
                            mma16816(acc[mt][nn], al[mt], bh[2 * j], bh[2 * j + 1]);
                        }
                    }
                }
            }
        }
        __syncthreads();   // S3: P3 reads done before next P1/P2 overwrite
    }

    // ---- epilogue: scatter ----
#pragma unroll
    for (int mt = 0; mt < 2; mt++) {
        int r0 = m0 + mt * 16 + (lane >> 2);
        int r1 = r0 + 8;
        int tg0 = tgt_s[r0], tg1 = tgt_s[r1];
        float* p0 = out + (size_t)(tg0 < 0 ? 0 : tg0) * WDIM;
        float* p1 = out + (size_t)(tg1 < 0 ? 0 : tg1) * WDIM;
#pragma unroll
        for (int nn = 0; nn < 4; nn++) {
            int col = n0 + nn * 8 + (lane & 3) * 2;
            if (tg0 >= 0)
                asm volatile("red.global.add.v2.f32 [%0], {%1,%2};" ::
                             "l"(p0 + col), "f"(acc[mt][nn][0]), "f"(acc[mt][nn][1]) : "memory");
            if (tg1 >= 0)
                asm volatile("red.global.add.v2.f32 [%0], {%1,%2};" ::
                             "l"(p1 + col), "f"(acc[mt][nn][2]), "f"(acc[mt][nn][3]) : "memory");
        }
    }
}

// ---------------------------------------------------------------------------
// K3: out[n,j] *= deg[n]^deg_param[j]
// ---------------------------------------------------------------------------
extern "C" __global__ void scale_kernel(float* __restrict__ out,
                                        const float* __restrict__ deg,
                                        const float* __restrict__ dp, int N)
{
    int idx = blockIdx.x * blockDim.x + threadIdx.x;
    if (idx < N * WDIM) {
        int n = idx >> 8, j = idx & 255;
        out[idx] *= __powf(__ldg(deg + n), __ldg(dp + j));
    }
}

// ---------------------------------------------------------------------------
extern "C" void kernel_launch(void* const* d_in, const int* in_sizes, int n_in,
                              void* d_out, int out_size)
{
    const float* x    = (const float*)d_in[0];
    const float* deg  = (const float*)d_in[1];
    const int*   eidx = (const int*)d_in[2];
    const int*   eattr= (const int*)d_in[3];
    const float* Wsrc = (const float*)d_in[4];
    const float* Wtgt = (const float*)d_in[5];
    const float* emb  = (const float*)d_in[6];
    const float* Wg   = (const float*)d_in[7];
    const float* Wv   = (const float*)d_in[8];
    const float* Wp   = (const float*)d_in[9];
    const float* dp   = (const float*)d_in[10];
    float* out = (float*)d_out;

    int N = in_sizes[0] / WDIM;
    int E = in_sizes[2] / 2;

    const int NODE_SMEM  = (16640 + 8192) * 4;      // 99328 B
    const int FUSED_SMEM = 181248;

    cudaFuncSetAttribute(node_gemm_kernel,
                         cudaFuncAttributeMaxDynamicSharedMemorySize, NODE_SMEM);
    cudaFuncSetAttribute(fused_edge_kernel,
                         cudaFuncAttributeMaxDynamicSharedMemorySize, FUSED_SMEM);

    cudaMemsetAsync(d_out, 0, (size_t)out_size * sizeof(float));

    wsplit_kernel<<<64, 1024>>>(Wp, Wg, Wv);
    dim3 ng((N + 63) / 64, 2);
    node_gemm_kernel<<<ng, 512, NODE_SMEM>>>(x, Wsrc, Wtgt, N);
    fused_edge_kernel<<<(E + 63) / 64, 512, FUSED_SMEM>>>(eidx, eattr, emb, out, E);
    scale_kernel<<<((size_t)N * WDIM + 511) / 512, 512>>>(out, deg, dp, N);
}

// round 7
// speedup vs baseline: 1.2791x; 1.2791x over previous
#include <cuda_runtime.h>
#include <cuda_bf16.h>
#include <cstdint>

#define WDIM 256

// ---------------------------------------------------------------------------
// Scratch (device globals)
// ---------------------------------------------------------------------------
__device__ float g_xs[2560000];            // [N,256]
__device__ float g_xt[2560000];
__device__ unsigned short g_wp_hi[65536];  // W_post bf16 hi [n,k]
__device__ unsigned short g_wp_lo[65536];
// packed gate/val weights per chunk: [c][row=hl*32+f][ Wg d0..31 | Wv d0..31 ]
__device__ unsigned short g_wgv_hi[16384];
__device__ unsigned short g_wgv_lo[16384];

typedef unsigned long long u64;

__device__ __forceinline__ void lds_v2u64(u64 &lo, u64 &hi, unsigned addr) {
    asm volatile("ld.shared.v2.u64 {%0,%1}, [%2];" : "=l"(lo), "=l"(hi) : "r"(addr));
}
__device__ __forceinline__ u64 ffma2(u64 a, u64 b, u64 c) {
    u64 d;
    asm("fma.rn.f32x2 %0, %1, %2, %3;" : "=l"(d) : "l"(a), "l"(b), "l"(c));
    return d;
}
__device__ __forceinline__ float unpack_sum(u64 p) {
    unsigned lo, hi;
    asm("mov.b64 {%0,%1}, %2;" : "=r"(lo), "=r"(hi) : "l"(p));
    return __uint_as_float(lo) + __uint_as_float(hi);
}
__device__ __forceinline__ unsigned sw128(unsigned x) { return x ^ ((x >> 3) & 0x70u); }
__device__ __forceinline__ void cpa16(unsigned dst, const void* src) {
    asm volatile("cp.async.cg.shared.global [%0], [%1], 16;" :: "r"(dst), "l"(src));
}
__device__ __forceinline__ void ldm_x4(unsigned* r, unsigned addr) {
    asm volatile("ldmatrix.sync.aligned.m8n8.x4.shared.b16 {%0,%1,%2,%3}, [%4];"
                 : "=r"(r[0]), "=r"(r[1]), "=r"(r[2]), "=r"(r[3]) : "r"(addr));
}
__device__ __forceinline__ void mma16816(float* d, const unsigned* a,
                                         unsigned b0, unsigned b1) {
    asm volatile(
        "mma.sync.aligned.m16n8k16.row.col.f32.bf16.bf16.f32 "
        "{%0,%1,%2,%3}, {%4,%5,%6,%7}, {%8,%9}, {%0,%1,%2,%3};"
        : "+f"(d[0]), "+f"(d[1]), "+f"(d[2]), "+f"(d[3])
        : "r"(a[0]), "r"(a[1]), "r"(a[2]), "r"(a[3]), "r"(b0), "r"(b1));
}
// pack 2 fp32 -> bf16x2 (hi16 = a1, lo16 = a0)
__device__ __forceinline__ unsigned bf2(float a1, float a0) {
    unsigned d;
    asm("cvt.rn.bf16x2.f32 %0, %1, %2;" : "=r"(d) : "f"(a1), "f"(a0));
    return d;
}

// ---------------------------------------------------------------------------
// K1: node GEMM (fp32 FFMA2) — unchanged
// ---------------------------------------------------------------------------
extern "C" __global__ void __launch_bounds__(512, 1)
node_gemm_kernel(const float* __restrict__ x,
                 const float* __restrict__ Wsrc,
                 const float* __restrict__ Wtgt, int N)
{
    extern __shared__ float sm[];
    float4* a4 = reinterpret_cast<float4*>(sm);
    float4* w4 = reinterpret_cast<float4*>(sm + 16640);
    const float* Wm = blockIdx.y ? Wtgt : Wsrc;
    float* og = blockIdx.y ? g_xt : g_xs;

    const int t  = threadIdx.x;
    const int nb = blockIdx.x * 64;

#pragma unroll
    for (int r = 0; r < 8; r++) {
        int id = t + 512 * r;
        int row = id >> 6, c4 = id & 63;
        int n = nb + row;
        float4 v = make_float4(0.f, 0.f, 0.f, 0.f);
        if (n < N) v = __ldg(reinterpret_cast<const float4*>(x + (size_t)n * WDIM) + c4);
        a4[row * 65 + c4] = v;
    }

    const int et = t >> 5, jt = t & 31;
    unsigned sa = (unsigned)__cvta_generic_to_shared(sm);
    unsigned sw = sa + 16640u * 4u;

    u64 accp[4][8];
#pragma unroll
    for (int ee = 0; ee < 4; ee++)
#pragma unroll
        for (int jj = 0; jj < 8; jj++) accp[ee][jj] = 0ull;

#pragma unroll 1
    for (int kt = 0; kt < 8; kt++) {
        __syncthreads();
#pragma unroll
        for (int r = 0; r < 4; r++) {
            int id = t + 512 * r;
            int j = id >> 3, kq = id & 7;
            w4[j * 8 + (kq ^ ((j >> 3) & 7))] =
                __ldg(reinterpret_cast<const float4*>(Wm + (size_t)j * WDIM + kt * 32) + kq);
        }
        __syncthreads();
#pragma unroll
        for (int kq = 0; kq < 8; kq++) {
            u64 aL[4], aH[4];
#pragma unroll
            for (int ee = 0; ee < 4; ee++)
                lds_v2u64(aL[ee], aH[ee],
                          sa + (unsigned)(((et * 4 + ee) * 65 + kt * 8 + kq) * 16));
#pragma unroll
            for (int half = 0; half < 2; half++) {
                u64 bL[4], bH[4];
#pragma unroll
                for (int jj = 0; jj < 4; jj++)
                    lds_v2u64(bL[jj], bH[jj],
                              sw + (unsigned)(((jt * 8 + half * 4 + jj) * 8 + (kq ^ (jt & 7))) * 16));
#pragma unroll
                for (int ee = 0; ee < 4; ee++)
#pragma unroll
                    for (int jj = 0; jj < 4; jj++)
                        accp[ee][half * 4 + jj] =
                            ffma2(aH[ee], bH[jj], ffma2(aL[ee], bL[jj], accp[ee][half * 4 + jj]));
            }
        }
    }

#pragma unroll
    for (int ee = 0; ee < 4; ee++) {
        int n = nb + et * 4 + ee;
        if (n >= N) continue;
        float r0 = unpack_sum(accp[ee][0]), r1 = unpack_sum(accp[ee][1]);
        float r2 = unpack_sum(accp[ee][2]), r3 = unpack_sum(accp[ee][3]);
        float r4 = unpack_sum(accp[ee][4]), r5 = unpack_sum(accp[ee][5]);
        float r6 = unpack_sum(accp[ee][6]), r7 = unpack_sum(accp[ee][7]);
        float4* py = reinterpret_cast<float4*>(og + (size_t)n * WDIM + jt * 8);
        py[0] = make_float4(r0, r1, r2, r3);
        py[1] = make_float4(r4, r5, r6, r7);
    }
}

// ---------------------------------------------------------------------------
// Weight preprocessing (R5 layout): W_post hi/lo + Wg/Wv packed per-chunk
// ---------------------------------------------------------------------------
extern "C" __global__ void wsplit_kernel(const float* __restrict__ Wp,
                                         const float* __restrict__ Wg,
                                         const float* __restrict__ Wv)
{
    int i = blockIdx.x * blockDim.x + threadIdx.x;
    if (i < 65536) {
        float v = Wp[i];
        __nv_bfloat16 h = __float2bfloat16(v);
        float lof = v - __bfloat162float(h);
        __nv_bfloat16 l = __float2bfloat16(lof);
        g_wp_hi[i] = *reinterpret_cast<unsigned short*>(&h);
        g_wp_lo[i] = *reinterpret_cast<unsigned short*>(&l);
    }
    if (i < 16384) {
        // layout: ((c*64 + row)*64 + gv*32 + d); row = hl*32 + f; h = c*2+hl
        int c   = i >> 12;
        int row = (i >> 6) & 63;
        int gv  = (i >> 5) & 1;
        int d   = i & 31;
        int h   = c * 2 + (row >> 5);
        int f   = row & 31;
        const float* Wm = gv ? Wv : Wg;
        float v = Wm[(size_t)h * 1024 + f * 32 + d];
        __nv_bfloat16 hh = __float2bfloat16(v);
        float lof = v - __bfloat162float(hh);
        __nv_bfloat16 ll = __float2bfloat16(lof);
        g_wgv_hi[i] = *reinterpret_cast<unsigned short*>(&hh);
        g_wgv_lo[i] = *reinterpret_cast<unsigned short*>(&ll);
    }
}

// ---------------------------------------------------------------------------
// K2 (fused), R7 = R5 arithmetic + double-buffered WP & WGV staging.
// smem (bytes):
//  tgt@0(pad 1024) | XNH@1024 XNL@9216 GINH@17408 GINL@25600
//  | ACTH@33792 ACTL@41984
//  | WGV buf0 hi@50176 lo@58368 | buf1 hi@66560 lo@74752
//  | WP  buf0 hi@82944 lo@115712 | buf1 hi@148480 lo@181248
//  total 246784? no: 148480+65536 = 214016 B total.
// ---------------------------------------------------------------------------
#define XNH_O  1024u
#define XNL_O  9216u
#define GINH_O 17408u
#define GINL_O 25600u
#define ACTH_O 33792u
#define ACTL_O 41984u
#define WGV_O  50176u
#define WGVBUF 16384u
#define WP_O   82944u
#define WPBUF  65536u

extern "C" __global__ void __launch_bounds__(512, 1)
fused_edge_kernel(const int* __restrict__ eidx, const int* __restrict__ eattr,
                  const float* __restrict__ emb, float* __restrict__ out, int E)
{
    extern __shared__ char smc[];
    unsigned sb = (unsigned)__cvta_generic_to_shared(smc);
    int* tgt_s = reinterpret_cast<int*>(smc);
    const int t = threadIdx.x, lane = t & 31, wid = t >> 5;
    const int eb = blockIdx.x * 64;

    if (t < 64) {
        int e = eb + t;
        tgt_s[t] = (e < E) ? __ldg(eidx + E + e) : -1;
    }

    // W_post warp tile 32x32: 16 warps = 2m x 8n
    const int wm = wid & 1, wn = wid >> 1;
    const int m0 = wm * 32, n0 = wn * 32;
    float acc[2][4][4];
#pragma unroll
    for (int mt = 0; mt < 2; mt++)
#pragma unroll
        for (int nn = 0; nn < 4; nn++)
#pragma unroll
            for (int q = 0; q < 4; q++) acc[mt][nn][q] = 0.f;

    const int e_l = t >> 3, sub = t & 7;
    const int e = eb + e_l;
    const int eg = wid >> 2, hl = (wid >> 1) & 1, nh = wid & 1;

    // ---- stage W_post + WGV chunk cc into buffer cc&1 (one commit group) ----
    auto stage = [&](int cc) {
        unsigned wpb = sb + WP_O + (unsigned)(cc & 1) * WPBUF;
#pragma unroll
        for (int i = 0; i < 4; i++) {
            int u = t + 512 * i;
            int n = u >> 3, q = u & 7;
            unsigned off = sw128((unsigned)(n * 128 + q * 16));
            cpa16(wpb + off,          g_wp_hi + (size_t)n * 256 + cc * 64 + q * 8);
            cpa16(wpb + 32768u + off, g_wp_lo + (size_t)n * 256 + cc * 64 + q * 8);
        }
        {
            unsigned wgb = sb + WGV_O + (unsigned)(cc & 1) * WGVBUF;
            int r = t >> 3, q = t & 7;
            unsigned off = sw128((unsigned)(r * 128 + q * 16));
            cpa16(wgb + off,         g_wgv_hi + (size_t)(cc * 64 + r) * 64 + q * 8);
            cpa16(wgb + 8192u + off, g_wgv_lo + (size_t)(cc * 64 + r) * 64 + q * 8);
        }
        asm volatile("cp.async.commit_group;" ::: "memory");
    };

    stage(0);
    __syncthreads();   // tgt_s visible to all warps before P1 reads it

#pragma unroll 1
    for (int c = 0; c < 4; c++) {
        if (c < 3) stage(c + 1);

        // ---- P1: xn/gin for this chunk's 2 heads ----
        {
            unsigned soff = sw128((unsigned)(e_l * 128 + sub * 16));
            if (e < E) {
                int s  = __ldg(eidx + e);
                int tg = tgt_s[e_l];
                const float4* ps = reinterpret_cast<const float4*>(
                    g_xs + (size_t)s * WDIM + c * 64 + sub * 8);
                const float4* pt = reinterpret_cast<const float4*>(
                    g_xt + (size_t)tg * WDIM + c * 64 + sub * 8);
                float xx[8];
                float4 a0 = ps[0], a1 = ps[1], b0 = pt[0], b1 = pt[1];
                xx[0] = a0.x + b0.x; xx[1] = a0.y + b0.y; xx[2] = a0.z + b0.z; xx[3] = a0.w + b0.w;
                xx[4] = a1.x + b1.x; xx[5] = a1.y + b1.y; xx[6] = a1.z + b1.z; xx[7] = a1.w + b1.w;
                float sum = 0.f, sq = 0.f;
#pragma unroll
                for (int i = 0; i < 8; i++) { sum += xx[i]; sq += xx[i] * xx[i]; }
                sum += __shfl_xor_sync(0xFFFFFFFFu, sum, 1);
                sq  += __shfl_xor_sync(0xFFFFFFFFu, sq, 1);
                sum += __shfl_xor_sync(0xFFFFFFFFu, sum, 2);
                sq  += __shfl_xor_sync(0xFFFFFFFFu, sq, 2);
                float mu = sum * (1.f / 32.f);
                float var = sq * (1.f / 32.f) - mu * mu;
                float rstd = rsqrtf(var + 1e-5f);

                float bag[8];
#pragma unroll
                for (int i = 0; i < 8; i++) bag[i] = 0.f;
                float cnt = 0.f;
#pragma unroll
                for (int b = 0; b < 3; b++) {
                    int a = __ldg(eattr + (size_t)e * 3 + b);
                    if (a != 0) {
                        cnt += 1.f;
                        const float4* pe = reinterpret_cast<const float4*>(
                            emb + (size_t)a * WDIM + c * 64 + sub * 8);
                        float4 e0 = __ldg(pe), e1 = __ldg(pe + 1);
                        bag[0] += e0.x; bag[1] += e0.y; bag[2] += e0.z; bag[3] += e0.w;
                        bag[4] += e1.x; bag[5] += e1.y; bag[6] += e1.z; bag[7] += e1.w;
                    }
                }
                float inv = 1.f / fmaxf(cnt, 1.f);
                float xn[8], gn[8];
#pragma unroll
                for (int i = 0; i < 8; i++) {
                    xn[i] = (xx[i] - mu) * rstd;
                    gn[i] = xn[i] + bag[i] * inv;
                }
                unsigned xh[4], xl[4], gh[4], gl[4];
#pragma unroll
                for (int p = 0; p < 4; p++) {
                    unsigned hp = bf2(xn[2 * p + 1], xn[2 * p]);
                    float h0 = __uint_as_float(hp << 16);
                    float h1 = __uint_as_float(hp & 0xFFFF0000u);
                    xh[p] = hp;
                    xl[p] = bf2(xn[2 * p + 1] - h1, xn[2 * p] - h0);
                    hp = bf2(gn[2 * p + 1], gn[2 * p]);
                    h0 = __uint_as_float(hp << 16);
                    h1 = __uint_as_float(hp & 0xFFFF0000u);
                    gh[p] = hp;
                    gl[p] = bf2(gn[2 * p + 1] - h1, gn[2 * p] - h0);
                }
                asm volatile("st.shared.v4.b32 [%0], {%1,%2,%3,%4};" ::
                             "r"(sb + XNH_O + soff), "r"(xh[0]), "r"(xh[1]), "r"(xh[2]), "r"(xh[3]));
                asm volatile("st.shared.v4.b32 [%0], {%1,%2,%3,%4};" ::
                             "r"(sb + XNL_O + soff), "r"(xl[0]), "r"(xl[1]), "r"(xl[2]), "r"(xl[3]));
                asm volatile("st.shared.v4.b32 [%0], {%1,%2,%3,%4};" ::
                             "r"(sb + GINH_O + soff), "r"(gh[0]), "r"(gh[1]), "r"(gh[2]), "r"(gh[3]));
                asm volatile("st.shared.v4.b32 [%0], {%1,%2,%3,%4};" ::
                             "r"(sb + GINL_O + soff), "r"(gl[0]), "r"(gl[1]), "r"(gl[2]), "r"(gl[3]));
            } else {
                asm volatile("st.shared.v4.b32 [%0], {%1,%1,%1,%1};" :: "r"(sb + XNH_O + soff), "r"(0u));
                asm volatile("st.shared.v4.b32 [%0], {%1,%1,%1,%1};" :: "r"(sb + XNL_O + soff), "r"(0u));
                asm volatile("st.shared.v4.b32 [%0], {%1,%1,%1,%1};" :: "r"(sb + GINH_O + soff), "r"(0u));
                asm volatile("st.shared.v4.b32 [%0], {%1,%1,%1,%1};" :: "r"(sb + GINL_O + soff), "r"(0u));
            }
        }
        // wait for group{c} (WP c + WGV c staged a full chunk ago)
        if (c < 3) {
            asm volatile("cp.async.wait_group 1;" ::: "memory");
        } else {
            asm volatile("cp.async.wait_group 0;" ::: "memory");
        }
        __syncthreads();   // S1: xn/gin + staged weights visible

        // ---- P2: gate/val HMMA (3-split) from smem WGV buf ----
        {
            unsigned wgb = sb + WGV_O + (unsigned)(c & 1) * WGVBUF;
            unsigned agh[2][4], agl[2][4], axh[2][4], axl[2][4];
            unsigned arow = (unsigned)((eg * 16 + (lane & 15)) * 128 + hl * 64 + (lane >> 4) * 16);
#pragma unroll
            for (int ks = 0; ks < 2; ks++) {
                unsigned off = sw128(arow + ks * 32);
                ldm_x4(agh[ks], sb + GINH_O + off);
                ldm_x4(agl[ks], sb + GINL_O + off);
                ldm_x4(axh[ks], sb + XNH_O + off);
                ldm_x4(axl[ks], sb + XNL_O + off);
            }
            unsigned brow = (unsigned)((hl * 32 + nh * 16 + (lane & 7) + ((lane >> 4) & 1) * 8) * 128
                                       + ((lane >> 3) & 1) * 16);
            unsigned bgh[2][4], bgl[2][4], bvh[2][4], bvl[2][4];
#pragma unroll
            for (int ks = 0; ks < 2; ks++) {
                unsigned offg = sw128(brow + ks * 32);
                unsigned offv = sw128(brow + 64 + ks * 32);
                ldm_x4(bgh[ks], wgb + offg);
                ldm_x4(bgl[ks], wgb + 8192u + offg);
                ldm_x4(bvh[ks], wgb + offv);
                ldm_x4(bvl[ks], wgb + 8192u + offv);
            }
            float gacc[2][4], vacc[2][4];
#pragma unroll
            for (int j = 0; j < 2; j++)
#pragma unroll
                for (int q = 0; q < 4; q++) { gacc[j][q] = 0.f; vacc[j][q] = 0.f; }
#pragma unroll
            for (int ks = 0; ks < 2; ks++)
#pragma unroll
                for (int j = 0; j < 2; j++) {
                    mma16816(gacc[j], agh[ks], bgh[ks][2 * j], bgh[ks][2 * j + 1]);
                    mma16816(gacc[j], agh[ks], bgl[ks][2 * j], bgl[ks][2 * j + 1]);
                    mma16816(gacc[j], agl[ks], bgh[ks][2 * j], bgh[ks][2 * j + 1]);
                    mma16816(vacc[j], axh[ks], bvh[ks][2 * j], bvh[ks][2 * j + 1]);
                    mma16816(vacc[j], axh[ks], bvl[ks][2 * j], bvl[ks][2 * j + 1]);
                    mma16816(vacc[j], axl[ks], bvh[ks][2 * j], bvh[ks][2 * j + 1]);
                }
#pragma unroll
            for (int j = 0; j < 2; j++)
#pragma unroll
                for (int half = 0; half < 2; half++) {
                    float a0 = fmaxf(gacc[j][half * 2], 0.f) * vacc[j][half * 2];
                    float a1 = fmaxf(gacc[j][half * 2 + 1], 0.f) * vacc[j][half * 2 + 1];
                    int row = eg * 16 + (lane >> 2) + half * 8;
                    int col = hl * 32 + nh * 16 + j * 8 + (lane & 3) * 2;
                    unsigned off = sw128((unsigned)(row * 128 + col * 2));
                    unsigned hp = bf2(a1, a0);
                    float h0 = __uint_as_float(hp << 16);
                    float h1 = __uint_as_float(hp & 0xFFFF0000u);
                    unsigned lp = bf2(a1 - h1, a0 - h0);
                    asm volatile("st.shared.b32 [%0], %1;" :: "r"(sb + ACTH_O + off), "r"(hp));
                    asm volatile("st.shared.b32 [%0], %1;" :: "r"(sb + ACTL_O + off), "r"(lp));
                }
        }
        __syncthreads();   // S2: act visible

        // ---- P3: W_post chunk mainloop ----
        {
            unsigned wpb = sb + WP_O + (unsigned)(c & 1) * WPBUF;
#pragma unroll
            for (int ks = 0; ks < 4; ks++) {
                unsigned ah[2][4], al[2][4];
#pragma unroll
                for (int mt = 0; mt < 2; mt++) {
                    unsigned off = sw128((unsigned)((m0 + mt * 16 + (lane & 15)) * 128
                                                    + ks * 32 + (lane >> 4) * 16));
                    ldm_x4(ah[mt], sb + ACTH_O + off);
                    ldm_x4(al[mt], sb + ACTL_O + off);
                }
#pragma unroll
                for (int nt = 0; nt < 2; nt++) {
                    unsigned off = sw128((unsigned)((n0 + nt * 16 + (lane & 7)
                                                     + ((lane >> 4) & 1) * 8) * 128
                                                    + ks * 32 + ((lane >> 3) & 1) * 16));
                    unsigned bh[4], bl[4];
                    ldm_x4(bh, wpb + off);
                    ldm_x4(bl, wpb + 32768u + off);
#pragma unroll
                    for (int j = 0; j < 2; j++) {
                        int nn = nt * 2 + j;
#pragma unroll
                        for (int mt = 0; mt < 2; mt++) {
                            mma16816(acc[mt][nn], ah[mt], bh[2 * j], bh[2 * j + 1]);
                            mma16816(acc[mt][nn], ah[mt], bl[2 * j], bl[2 * j + 1]);
                            mma16816(acc[mt][nn], al[mt], bh[2 * j], bh[2 * j + 1]);
                        }
                    }
                }
            }
        }
        __syncthreads();   // S3: P3 reads done before next chunk overwrites act/xn
    }

    // ---- epilogue: scatter ----
#pragma unroll
    for (int mt = 0; mt < 2; mt++) {
        int r0 = m0 + mt * 16 + (lane >> 2);
        int r1 = r0 + 8;
        int tg0 = tgt_s[r0], tg1 = tgt_s[r1];
        float* p0 = out + (size_t)(tg0 < 0 ? 0 : tg0) * WDIM;
        float* p1 = out + (size_t)(tg1 < 0 ? 0 : tg1) * WDIM;
#pragma unroll
        for (int nn = 0; nn < 4; nn++) {
            int col = n0 + nn * 8 + (lane & 3) * 2;
            if (tg0 >= 0)
                asm volatile("red.global.add.v2.f32 [%0], {%1,%2};" ::
                             "l"(p0 + col), "f"(acc[mt][nn][0]), "f"(acc[mt][nn][1]) : "memory");
            if (tg1 >= 0)
                asm volatile("red.global.add.v2.f32 [%0], {%1,%2};" ::
                             "l"(p1 + col), "f"(acc[mt][nn][2]), "f"(acc[mt][nn][3]) : "memory");
        }
    }
}

// ---------------------------------------------------------------------------
// K3: out[n,j] *= deg[n]^deg_param[j]
// ---------------------------------------------------------------------------
extern "C" __global__ void scale_kernel(float* __restrict__ out,
                                        const float* __restrict__ deg,
                                        const float* __restrict__ dp, int N)
{
    int idx = blockIdx.x * blockDim.x + threadIdx.x;
    if (idx < N * WDIM) {
        int n = idx >> 8, j = idx & 255;
        out[idx] *= __powf(__ldg(deg + n), __ldg(dp + j));
    }
}

// ---------------------------------------------------------------------------
extern "C" void kernel_launch(void* const* d_in, const int* in_sizes, int n_in,
                              void* d_out, int out_size)
{
    const float* x    = (const float*)d_in[0];
    const float* deg  = (const float*)d_in[1];
    const int*   eidx = (const int*)d_in[2];
    const int*   eattr= (const int*)d_in[3];
    const float* Wsrc = (const float*)d_in[4];
    const float* Wtgt = (const float*)d_in[5];
    const float* emb  = (const float*)d_in[6];
    const float* Wg   = (const float*)d_in[7];
    const float* Wv   = (const float*)d_in[8];
    const float* Wp   = (const float*)d_in[9];
    const float* dp   = (const float*)d_in[10];
    float* out = (float*)d_out;

    int N = in_sizes[0] / WDIM;
    int E = in_sizes[2] / 2;

    const int NODE_SMEM  = (16640 + 8192) * 4;      // 99328 B
    const int FUSED_SMEM = 214016;                  // see layout comment

    cudaFuncSetAttribute(node_gemm_kernel,
                         cudaFuncAttributeMaxDynamicSharedMemorySize, NODE_SMEM);
    cudaFuncSetAttribute(fused_edge_kernel,
                         cudaFuncAttributeMaxDynamicSharedMemorySize, FUSED_SMEM);

    cudaMemsetAsync(d_out, 0, (size_t)out_size * sizeof(float));

    wsplit_kernel<<<64, 1024>>>(Wp, Wg, Wv);
    dim3 ng((N + 63) / 64, 2);
    node_gemm_kernel<<<ng, 512, NODE_SMEM>>>(x, Wsrc, Wtgt, N);
    fused_edge_kernel<<<(E + 63) / 64, 512, FUSED_SMEM>>>(eidx, eattr, emb, out, E);
    scale_kernel<<<((size_t)N * WDIM + 511) / 512, 512>>>(out, deg, dp, N);
}

// round 8
// speedup vs baseline: 1.2836x; 1.0035x over previous
#include <cuda_runtime.h>
#include <cuda_bf16.h>
#include <cstdint>

#define WDIM 256

// ---------------------------------------------------------------------------
// Scratch (device globals)
// ---------------------------------------------------------------------------
__device__ float g_xs[2560000];            // [N,256]
__device__ float g_xt[2560000];
__device__ unsigned short g_wp_hi[65536];  // W_post bf16 hi [n,k]
__device__ unsigned short g_wp_lo[65536];
// packed gate/val weights per chunk: [c][row=hl*32+f][ Wg d0..31 | Wv d0..31 ]
__device__ unsigned short g_wgv_hi[16384];
__device__ unsigned short g_wgv_lo[16384];

typedef unsigned long long u64;

__device__ __forceinline__ void lds_v2u64(u64 &lo, u64 &hi, unsigned addr) {
    asm volatile("ld.shared.v2.u64 {%0,%1}, [%2];" : "=l"(lo), "=l"(hi) : "r"(addr));
}
__device__ __forceinline__ u64 ffma2(u64 a, u64 b, u64 c) {
    u64 d;
    asm("fma.rn.f32x2 %0, %1, %2, %3;" : "=l"(d) : "l"(a), "l"(b), "l"(c));
    return d;
}
__device__ __forceinline__ float unpack_sum(u64 p) {
    unsigned lo, hi;
    asm("mov.b64 {%0,%1}, %2;" : "=r"(lo), "=r"(hi) : "l"(p));
    return __uint_as_float(lo) + __uint_as_float(hi);
}
__device__ __forceinline__ unsigned sw128(unsigned x) { return x ^ ((x >> 3) & 0x70u); }
__device__ __forceinline__ void cpa16(unsigned dst, const void* src) {
    asm volatile("cp.async.cg.shared.global [%0], [%1], 16;" :: "r"(dst), "l"(src));
}
__device__ __forceinline__ void zfill16(unsigned dst) {
    asm volatile("st.shared.v4.b32 [%0], {%1,%1,%1,%1};" :: "r"(dst), "r"(0u));
}
__device__ __forceinline__ void ldm_x4(unsigned* r, unsigned addr) {
    asm volatile("ldmatrix.sync.aligned.m8n8.x4.shared.b16 {%0,%1,%2,%3}, [%4];"
                 : "=r"(r[0]), "=r"(r[1]), "=r"(r[2]), "=r"(r[3]) : "r"(addr));
}
__device__ __forceinline__ void mma16816(float* d, const unsigned* a,
                                         unsigned b0, unsigned b1) {
    asm volatile(
        "mma.sync.aligned.m16n8k16.row.col.f32.bf16.bf16.f32 "
        "{%0,%1,%2,%3}, {%4,%5,%6,%7}, {%8,%9}, {%0,%1,%2,%3};"
        : "+f"(d[0]), "+f"(d[1]), "+f"(d[2]), "+f"(d[3])
        : "r"(a[0]), "r"(a[1]), "r"(a[2]), "r"(a[3]), "r"(b0), "r"(b1));
}
// pack 2 fp32 -> bf16x2 (hi16 = a1, lo16 = a0)
__device__ __forceinline__ unsigned bf2(float a1, float a0) {
    unsigned d;
    asm("cvt.rn.bf16x2.f32 %0, %1, %2;" : "=r"(d) : "f"(a1), "f"(a0));
    return d;
}

// ---------------------------------------------------------------------------
// K1: node GEMM (fp32 FFMA2) — unchanged
// ---------------------------------------------------------------------------
extern "C" __global__ void __launch_bounds__(512, 1)
node_gemm_kernel(const float* __restrict__ x,
                 const float* __restrict__ Wsrc,
                 const float* __restrict__ Wtgt, int N)
{
    extern __shared__ float sm[];
    float4* a4 = reinterpret_cast<float4*>(sm);
    float4* w4 = reinterpret_cast<float4*>(sm + 16640);
    const float* Wm = blockIdx.y ? Wtgt : Wsrc;
    float* og = blockIdx.y ? g_xt : g_xs;

    const int t  = threadIdx.x;
    const int nb = blockIdx.x * 64;

#pragma unroll
    for (int r = 0; r < 8; r++) {
        int id = t + 512 * r;
        int row = id >> 6, c4 = id & 63;
        int n = nb + row;
        float4 v = make_float4(0.f, 0.f, 0.f, 0.f);
        if (n < N) v = __ldg(reinterpret_cast<const float4*>(x + (size_t)n * WDIM) + c4);
        a4[row * 65 + c4] = v;
    }

    const int et = t >> 5, jt = t & 31;
    unsigned sa = (unsigned)__cvta_generic_to_shared(sm);
    unsigned sw = sa + 16640u * 4u;

    u64 accp[4][8];
#pragma unroll
    for (int ee = 0; ee < 4; ee++)
#pragma unroll
        for (int jj = 0; jj < 8; jj++) accp[ee][jj] = 0ull;

#pragma unroll 1
    for (int kt = 0; kt < 8; kt++) {
        __syncthreads();
#pragma unroll
        for (int r = 0; r < 4; r++) {
            int id = t + 512 * r;
            int j = id >> 3, kq = id & 7;
            w4[j * 8 + (kq ^ ((j >> 3) & 7))] =
                __ldg(reinterpret_cast<const float4*>(Wm + (size_t)j * WDIM + kt * 32) + kq);
        }
        __syncthreads();
#pragma unroll
        for (int kq = 0; kq < 8; kq++) {
            u64 aL[4], aH[4];
#pragma unroll
            for (int ee = 0; ee < 4; ee++)
                lds_v2u64(aL[ee], aH[ee],
                          sa + (unsigned)(((et * 4 + ee) * 65 + kt * 8 + kq) * 16));
#pragma unroll
            for (int half = 0; half < 2; half++) {
                u64 bL[4], bH[4];
#pragma unroll
                for (int jj = 0; jj < 4; jj++)
                    lds_v2u64(bL[jj], bH[jj],
                              sw + (unsigned)(((jt * 8 + half * 4 + jj) * 8 + (kq ^ (jt & 7))) * 16));
#pragma unroll
                for (int ee = 0; ee < 4; ee++)
#pragma unroll
                    for (int jj = 0; jj < 4; jj++)
                        accp[ee][half * 4 + jj] =
                            ffma2(aH[ee], bH[jj], ffma2(aL[ee], bL[jj], accp[ee][half * 4 + jj]));
            }
        }
    }

#pragma unroll
    for (int ee = 0; ee < 4; ee++) {
        int n = nb + et * 4 + ee;
        if (n >= N) continue;
        float r0 = unpack_sum(accp[ee][0]), r1 = unpack_sum(accp[ee][1]);
        float r2 = unpack_sum(accp[ee][2]), r3 = unpack_sum(accp[ee][3]);
        float r4 = unpack_sum(accp[ee][4]), r5 = unpack_sum(accp[ee][5]);
        float r6 = unpack_sum(accp[ee][6]), r7 = unpack_sum(accp[ee][7]);
        float4* py = reinterpret_cast<float4*>(og + (size_t)n * WDIM + jt * 8);
        py[0] = make_float4(r0, r1, r2, r3);
        py[1] = make_float4(r4, r5, r6, r7);
    }
}

// ---------------------------------------------------------------------------
// Weight preprocessing (R5 layout): W_post hi/lo + Wg/Wv packed per-chunk
// ---------------------------------------------------------------------------
extern "C" __global__ void wsplit_kernel(const float* __restrict__ Wp,
                                         const float* __restrict__ Wg,
                                         const float* __restrict__ Wv)
{
    int i = blockIdx.x * blockDim.x + threadIdx.x;
    if (i < 65536) {
        float v = Wp[i];
        __nv_bfloat16 h = __float2bfloat16(v);
        float lof = v - __bfloat162float(h);
        __nv_bfloat16 l = __float2bfloat16(lof);
        g_wp_hi[i] = *reinterpret_cast<unsigned short*>(&h);
        g_wp_lo[i] = *reinterpret_cast<unsigned short*>(&l);
    }
    if (i < 16384) {
        int c   = i >> 12;
        int row = (i >> 6) & 63;
        int gv  = (i >> 5) & 1;
        int d   = i & 31;
        int h   = c * 2 + (row >> 5);
        int f   = row & 31;
        const float* Wm = gv ? Wv : Wg;
        float v = Wm[(size_t)h * 1024 + f * 32 + d];
        __nv_bfloat16 hh = __float2bfloat16(v);
        float lof = v - __bfloat162float(hh);
        __nv_bfloat16 ll = __float2bfloat16(lof);
        g_wgv_hi[i] = *reinterpret_cast<unsigned short*>(&hh);
        g_wgv_lo[i] = *reinterpret_cast<unsigned short*>(&ll);
    }
}

// ---------------------------------------------------------------------------
// K2 (fused), R8 = R5 arithmetic + cp.async-prefetched node gathers.
// smem (bytes):
//  tgt@0(256) src@256(256) pad->1024
//  XNH@1024 XNL@9216 GINH@17408 GINL@25600 (8K each)
//  ACTH@33792 ACTL@41984 (8K each)
//  WGV buf0 hi@50176 lo@58368 | buf1 hi@66560 lo@74752
//  WP hi@82944 lo@115712 (single buffer, 64K)
//  XSXT buf0 xs@148480 xt@164864 | buf1 xs@181248 xt@197632
//  total 214016
// ---------------------------------------------------------------------------
#define XNH_O  1024u
#define XNL_O  9216u
#define GINH_O 17408u
#define GINL_O 25600u
#define ACTH_O 33792u
#define ACTL_O 41984u
#define WGV_O  50176u
#define WGVBUF 16384u
#define WP_O   82944u
#define XS_O   148480u
#define XSBUF  32768u

extern "C" __global__ void __launch_bounds__(512, 1)
fused_edge_kernel(const int* __restrict__ eidx, const int* __restrict__ eattr,
                  const float* __restrict__ emb, float* __restrict__ out, int E)
{
    extern __shared__ char smc[];
    unsigned sb = (unsigned)__cvta_generic_to_shared(smc);
    int* tgt_s = reinterpret_cast<int*>(smc);
    int* src_s = reinterpret_cast<int*>(smc + 256);
    const int t = threadIdx.x, lane = t & 31, wid = t >> 5;
    const int eb = blockIdx.x * 64;

    if (t < 64) {
        int e = eb + t;
        if (e < E) {
            tgt_s[t] = __ldg(eidx + E + e);
            src_s[t] = __ldg(eidx + e);
        } else {
            tgt_s[t] = -1;
            src_s[t] = -1;
        }
    }
    __syncthreads();   // src/tgt visible before staging uses them

    const int wm = wid & 1, wn = wid >> 1;
    const int m0 = wm * 32, n0 = wn * 32;
    float acc[2][4][4];
#pragma unroll
    for (int mt = 0; mt < 2; mt++)
#pragma unroll
        for (int nn = 0; nn < 4; nn++)
#pragma unroll
            for (int q = 0; q < 4; q++) acc[mt][nn][q] = 0.f;

    const int e_l = t >> 3, sub = t & 7;
    const int e = eb + e_l;
    const int eg = wid >> 2, hl = (wid >> 1) & 1, nh = wid & 1;

    // ---- stage raw xs/xt rows + WGV for chunk cc into buffer cc&1 ----
    auto stage_xw = [&](int cc) {
        unsigned xb = sb + XS_O + (unsigned)(cc & 1) * XSBUF;
        // 64 rows x 16 segs (16B each) per array, 2 per thread per array
#pragma unroll
        for (int i = 0; i < 2; i++) {
            int u = t + 512 * i;
            int row = u >> 4, seg = u & 15;
            int pair = seg >> 1;
            unsigned dsto = (unsigned)(row * 256 + ((pair ^ (row & 7)) * 32) + (seg & 1) * 16);
            int s = src_s[row], tg = tgt_s[row];
            if (s >= 0) {
                cpa16(xb + dsto,           g_xs + (size_t)s  * WDIM + cc * 64 + seg * 4);
                cpa16(xb + 16384u + dsto,  g_xt + (size_t)tg * WDIM + cc * 64 + seg * 4);
            } else {
                zfill16(xb + dsto);
                zfill16(xb + 16384u + dsto);
            }
        }
        {
            unsigned wgb = sb + WGV_O + (unsigned)(cc & 1) * WGVBUF;
            int r = t >> 3, q = t & 7;
            unsigned off = sw128((unsigned)(r * 128 + q * 16));
            cpa16(wgb + off,         g_wgv_hi + (size_t)(cc * 64 + r) * 64 + q * 8);
            cpa16(wgb + 8192u + off, g_wgv_lo + (size_t)(cc * 64 + r) * 64 + q * 8);
        }
        asm volatile("cp.async.commit_group;" ::: "memory");
    };
    // ---- stage W_post chunk into the single WP buffer ----
    auto stage_wp = [&](int cc) {
#pragma unroll
        for (int i = 0; i < 4; i++) {
            int u = t + 512 * i;
            int n = u >> 3, q = u & 7;
            unsigned off = sw128((unsigned)(n * 128 + q * 16));
            cpa16(sb + WP_O + off,           g_wp_hi + (size_t)n * 256 + cc * 64 + q * 8);
            cpa16(sb + WP_O + 32768u + off,  g_wp_lo + (size_t)n * 256 + cc * 64 + q * 8);
        }
        asm volatile("cp.async.commit_group;" ::: "memory");
    };

    stage_xw(0);

#pragma unroll 1
    for (int c = 0; c < 4; c++) {
        stage_wp(c);
        if (c < 3) {
            stage_xw(c + 1);
            asm volatile("cp.async.wait_group 1;" ::: "memory");
        } else {
            asm volatile("cp.async.wait_group 0;" ::: "memory");
        }
        __syncthreads();   // S0: xs/xt(c), WGV(c), WP(c) all staged & visible

        // ---- P1: xn/gin from staged smem (no global gather latency) ----
        {
            unsigned soff = sw128((unsigned)(e_l * 128 + sub * 16));
            if (e < E) {
                int sub2 = sub ^ (e_l & 7);
                const float4* xsp = reinterpret_cast<const float4*>(
                    smc + XS_O + (unsigned)(c & 1) * XSBUF + (unsigned)(e_l * 256 + sub2 * 32));
                const float4* xtp = reinterpret_cast<const float4*>(
                    smc + XS_O + 16384u + (unsigned)(c & 1) * XSBUF + (unsigned)(e_l * 256 + sub2 * 32));
                float xx[8];
                float4 a0 = xsp[0], a1 = xsp[1], b0 = xtp[0], b1 = xtp[1];
                xx[0] = a0.x + b0.x; xx[1] = a0.y + b0.y; xx[2] = a0.z + b0.z; xx[3] = a0.w + b0.w;
                xx[4] = a1.x + b1.x; xx[5] = a1.y + b1.y; xx[6] = a1.z + b1.z; xx[7] = a1.w + b1.w;
                float sum = 0.f, sq = 0.f;
#pragma unroll
                for (int i = 0; i < 8; i++) { sum += xx[i]; sq += xx[i] * xx[i]; }
                sum += __shfl_xor_sync(0xFFFFFFFFu, sum, 1);
                sq  += __shfl_xor_sync(0xFFFFFFFFu, sq, 1);
                sum += __shfl_xor_sync(0xFFFFFFFFu, sum, 2);
                sq  += __shfl_xor_sync(0xFFFFFFFFu, sq, 2);
                float mu = sum * (1.f / 32.f);
                float var = sq * (1.f / 32.f) - mu * mu;
                float rstd = rsqrtf(var + 1e-5f);

                float bag[8];
#pragma unroll
                for (int i = 0; i < 8; i++) bag[i] = 0.f;
                float cnt = 0.f;
#pragma unroll
                for (int b = 0; b < 3; b++) {
                    int a = __ldg(eattr + (size_t)e * 3 + b);
                    if (a != 0) {
                        cnt += 1.f;
                        const float4* pe = reinterpret_cast<const float4*>(
                            emb + (size_t)a * WDIM + c * 64 + sub * 8);
                        float4 e0 = __ldg(pe), e1 = __ldg(pe + 1);
                        bag[0] += e0.x; bag[1] += e0.y; bag[2] += e0.z; bag[3] += e0.w;
                        bag[4] += e1.x; bag[5] += e1.y; bag[6] += e1.z; bag[7] += e1.w;
                    }
                }
                float inv = 1.f / fmaxf(cnt, 1.f);
                float xn[8], gn[8];
#pragma unroll
                for (int i = 0; i < 8; i++) {
                    xn[i] = (xx[i] - mu) * rstd;
                    gn[i] = xn[i] + bag[i] * inv;
                }
                unsigned xh[4], xl[4], gh[4], gl[4];
#pragma unroll
                for (int p = 0; p < 4; p++) {
                    unsigned hp = bf2(xn[2 * p + 1], xn[2 * p]);
                    float h0 = __uint_as_float(hp << 16);
                    float h1 = __uint_as_float(hp & 0xFFFF0000u);
                    xh[p] = hp;
                    xl[p] = bf2(xn[2 * p + 1] - h1, xn[2 * p] - h0);
                    hp = bf2(gn[2 * p + 1], gn[2 * p]);
                    h0 = __uint_as_float(hp << 16);
                    h1 = __uint_as_float(hp & 0xFFFF0000u);
                    gh[p] = hp;
                    gl[p] = bf2(gn[2 * p + 1] - h1, gn[2 * p] - h0);
                }
                asm volatile("st.shared.v4.b32 [%0], {%1,%2,%3,%4};" ::
                             "r"(sb + XNH_O + soff), "r"(xh[0]), "r"(xh[1]), "r"(xh[2]), "r"(xh[3]));
                asm volatile("st.shared.v4.b32 [%0], {%1,%2,%3,%4};" ::
                             "r"(sb + XNL_O + soff), "r"(xl[0]), "r"(xl[1]), "r"(xl[2]), "r"(xl[3]));
                asm volatile("st.shared.v4.b32 [%0], {%1,%2,%3,%4};" ::
                             "r"(sb + GINH_O + soff), "r"(gh[0]), "r"(gh[1]), "r"(gh[2]), "r"(gh[3]));
                asm volatile("st.shared.v4.b32 [%0], {%1,%2,%3,%4};" ::
                             "r"(sb + GINL_O + soff), "r"(gl[0]), "r"(gl[1]), "r"(gl[2]), "r"(gl[3]));
            } else {
                asm volatile("st.shared.v4.b32 [%0], {%1,%1,%1,%1};" :: "r"(sb + XNH_O + soff), "r"(0u));
                asm volatile("st.shared.v4.b32 [%0], {%1,%1,%1,%1};" :: "r"(sb + XNL_O + soff), "r"(0u));
                asm volatile("st.shared.v4.b32 [%0], {%1,%1,%1,%1};" :: "r"(sb + GINH_O + soff), "r"(0u));
                asm volatile("st.shared.v4.b32 [%0], {%1,%1,%1,%1};" :: "r"(sb + GINL_O + soff), "r"(0u));
            }
        }
        __syncthreads();   // S1: xn/gin visible

        // ---- P2: gate/val HMMA (3-split) from smem WGV buf ----
        {
            unsigned wgb = sb + WGV_O + (unsigned)(c & 1) * WGVBUF;
            unsigned agh[2][4], agl[2][4], axh[2][4], axl[2][4];
            unsigned arow = (unsigned)((eg * 16 + (lane & 15)) * 128 + hl * 64 + (lane >> 4) * 16);
#pragma unroll
            for (int ks = 0; ks < 2; ks++) {
                unsigned off = sw128(arow + ks * 32);
                ldm_x4(agh[ks], sb + GINH_O + off);
                ldm_x4(agl[ks], sb + GINL_O + off);
                ldm_x4(axh[ks], sb + XNH_O + off);
                ldm_x4(axl[ks], sb + XNL_O + off);
            }
            unsigned brow = (unsigned)((hl * 32 + nh * 16 + (lane & 7) + ((lane >> 4) & 1) * 8) * 128
                                       + ((lane >> 3) & 1) * 16);
            unsigned bgh[2][4], bgl[2][4], bvh[2][4], bvl[2][4];
#pragma unroll
            for (int ks = 0; ks < 2; ks++) {
                unsigned offg = sw128(brow + ks * 32);
                unsigned offv = sw128(brow + 64 + ks * 32);
                ldm_x4(bgh[ks], wgb + offg);
                ldm_x4(bgl[ks], wgb + 8192u + offg);
                ldm_x4(bvh[ks], wgb + offv);
                ldm_x4(bvl[ks], wgb + 8192u + offv);
            }
            float gacc[2][4], vacc[2][4];
#pragma unroll
            for (int j = 0; j < 2; j++)
#pragma unroll
                for (int q = 0; q < 4; q++) { gacc[j][q] = 0.f; vacc[j][q] = 0.f; }
#pragma unroll
            for (int ks = 0; ks < 2; ks++)
#pragma unroll
                for (int j = 0; j < 2; j++) {
                    mma16816(gacc[j], agh[ks], bgh[ks][2 * j], bgh[ks][2 * j + 1]);
                    mma16816(gacc[j], agh[ks], bgl[ks][2 * j], bgl[ks][2 * j + 1]);
                    mma16816(gacc[j], agl[ks], bgh[ks][2 * j], bgh[ks][2 * j + 1]);
                    mma16816(vacc[j], axh[ks], bvh[ks][2 * j], bvh[ks][2 * j + 1]);
                    mma16816(vacc[j], axh[ks], bvl[ks][2 * j], bvl[ks][2 * j + 1]);
                    mma16816(vacc[j], axl[ks], bvh[ks][2 * j], bvh[ks][2 * j + 1]);
                }
#pragma unroll
            for (int j = 0; j < 2; j++)
#pragma unroll
                for (int half = 0; half < 2; half++) {
                    float a0 = fmaxf(gacc[j][half * 2], 0.f) * vacc[j][half * 2];
                    float a1 = fmaxf(gacc[j][half * 2 + 1], 0.f) * vacc[j][half * 2 + 1];
                    int row = eg * 16 + (lane >> 2) + half * 8;
                    int col = hl * 32 + nh * 16 + j * 8 + (lane & 3) * 2;
                    unsigned off = sw128((unsigned)(row * 128 + col * 2));
                    unsigned hp = bf2(a1, a0);
                    float h0 = __uint_as_float(hp << 16);
                    float h1 = __uint_as_float(hp & 0xFFFF0000u);
                    unsigned lp = bf2(a1 - h1, a0 - h0);
                    asm volatile("st.shared.b32 [%0], %1;" :: "r"(sb + ACTH_O + off), "r"(hp));
                    asm volatile("st.shared.b32 [%0], %1;" :: "r"(sb + ACTL_O + off), "r"(lp));
                }
        }
        __syncthreads();   // S2: act visible

        // ---- P3: W_post chunk mainloop ----
        {
#pragma unroll
            for (int ks = 0; ks < 4; ks++) {
                unsigned ah[2][4], al[2][4];
#pragma unroll
                for (int mt = 0; mt < 2; mt++) {
                    unsigned off = sw128((unsigned)((m0 + mt * 16 + (lane & 15)) * 128
                                                    + ks * 32 + (lane >> 4) * 16));
                    ldm_x4(ah[mt], sb + ACTH_O + off);
                    ldm_x4(al[mt], sb + ACTL_O + off);
                }
#pragma unroll
                for (int nt = 0; nt < 2; nt++) {
                    unsigned off = sw128((unsigned)((n0 + nt * 16 + (lane & 7)
                                                     + ((lane >> 4) & 1) * 8) * 128
                                                    + ks * 32 + ((lane >> 3) & 1) * 16));
                    unsigned bh[4], bl[4];
                    ldm_x4(bh, sb + WP_O + off);
                    ldm_x4(bl, sb + WP_O + 32768u + off);
#pragma unroll
                    for (int j = 0; j < 2; j++) {
                        int nn = nt * 2 + j;
#pragma unroll
                        for (int mt = 0; mt < 2; mt++) {
                            mma16816(acc[mt][nn], ah[mt], bh[2 * j], bh[2 * j + 1]);
                            mma16816(acc[mt][nn], ah[mt], bl[2 * j], bl[2 * j + 1]);
                            mma16816(acc[mt][nn], al[mt], bh[2 * j], bh[2 * j + 1]);
                        }
                    }
                }
            }
        }
        __syncthreads();   // S3: P3 reads done before next chunk restages WP/act
    }

    // ---- epilogue: scatter ----
#pragma unroll
    for (int mt = 0; mt < 2; mt++) {
        int r0 = m0 + mt * 16 + (lane >> 2);
        int r1 = r0 + 8;
        int tg0 = tgt_s[r0], tg1 = tgt_s[r1];
        float* p0 = out + (size_t)(tg0 < 0 ? 0 : tg0) * WDIM;
        float* p1 = out + (size_t)(tg1 < 0 ? 0 : tg1) * WDIM;
#pragma unroll
        for (int nn = 0; nn < 4; nn++) {
            int col = n0 + nn * 8 + (lane & 3) * 2;
            if (tg0 >= 0)
                asm volatile("red.global.add.v2.f32 [%0], {%1,%2};" ::
                             "l"(p0 + col), "f"(acc[mt][nn][0]), "f"(acc[mt][nn][1]) : "memory");
            if (tg1 >= 0)
                asm volatile("red.global.add.v2.f32 [%0], {%1,%2};" ::
                             "l"(p1 + col), "f"(acc[mt][nn][2]), "f"(acc[mt][nn][3]) : "memory");
        }
    }
}

// ---------------------------------------------------------------------------
// K3: out[n,j] *= deg[n]^deg_param[j]
// ---------------------------------------------------------------------------
extern "C" __global__ void scale_kernel(float* __restrict__ out,
                                        const float* __restrict__ deg,
                                        const float* __restrict__ dp, int N)
{
    int idx = blockIdx.x * blockDim.x + threadIdx.x;
    if (idx < N * WDIM) {
        int n = idx >> 8, j = idx & 255;
        out[idx] *= __powf(__ldg(deg + n), __ldg(dp + j));
    }
}

// ---------------------------------------------------------------------------
extern "C" void kernel_launch(void* const* d_in, const int* in_sizes, int n_in,
                              void* d_out, int out_size)
{
    const float* x    = (const float*)d_in[0];
    const float* deg  = (const float*)d_in[1];
    const int*   eidx = (const int*)d_in[2];
    const int*   eattr= (const int*)d_in[3];
    const float* Wsrc = (const float*)d_in[4];
    const float* Wtgt = (const float*)d_in[5];
    const float* emb  = (const float*)d_in[6];
    const float* Wg   = (const float*)d_in[7];
    const float* Wv   = (const float*)d_in[8];
    const float* Wp   = (const float*)d_in[9];
    const float* dp   = (const float*)d_in[10];
    float* out = (float*)d_out;

    int N = in_sizes[0] / WDIM;
    int E = in_sizes[2] / 2;

    const int NODE_SMEM  = (16640 + 8192) * 4;      // 99328 B
    const int FUSED_SMEM = 214016;

    cudaFuncSetAttribute(node_gemm_kernel,
                         cudaFuncAttributeMaxDynamicSharedMemorySize, NODE_SMEM);
    cudaFuncSetAttribute(fused_edge_kernel,
                         cudaFuncAttributeMaxDynamicSharedMemorySize, FUSED_SMEM);

    cudaMemsetAsync(d_out, 0, (size_t)out_size * sizeof(float));

    wsplit_kernel<<<64, 1024>>>(Wp, Wg, Wv);
    dim3 ng((N + 63) / 64, 2);
    node_gemm_kernel<<<ng, 512, NODE_SMEM>>>(x, Wsrc, Wtgt, N);
    fused_edge_kernel<<<(E + 63) / 64, 512, FUSED_SMEM>>>(eidx, eattr, emb, out, E);
    scale_kernel<<<((size_t)N * WDIM + 511) / 512, 512>>>(out, deg, dp, N);
}

// round 9
// speedup vs baseline: 1.3864x; 1.0801x over previous
#include <cuda_runtime.h>
#include <cuda_bf16.h>
#include <cstdint>

#define WDIM 256

// ---------------------------------------------------------------------------
// Scratch (device globals)
// ---------------------------------------------------------------------------
__device__ float g_xs[2560000];            // [N,256]
__device__ float g_xt[2560000];
__device__ unsigned short g_wp_hi[65536];  // W_post bf16 hi [n,k]
__device__ unsigned short g_wp_lo[65536];
// packed gate/val weights per chunk: [c][row=hl*32+f][ Wg d0..31 | Wv d0..31 ]
__device__ unsigned short g_wgv_hi[16384];
__device__ unsigned short g_wgv_lo[16384];

typedef unsigned long long u64;

__device__ __forceinline__ void lds_v2u64(u64 &lo, u64 &hi, unsigned addr) {
    asm volatile("ld.shared.v2.u64 {%0,%1}, [%2];" : "=l"(lo), "=l"(hi) : "r"(addr));
}
__device__ __forceinline__ u64 ffma2(u64 a, u64 b, u64 c) {
    u64 d;
    asm("fma.rn.f32x2 %0, %1, %2, %3;" : "=l"(d) : "l"(a), "l"(b), "l"(c));
    return d;
}
__device__ __forceinline__ float unpack_sum(u64 p) {
    unsigned lo, hi;
    asm("mov.b64 {%0,%1}, %2;" : "=r"(lo), "=r"(hi) : "l"(p));
    return __uint_as_float(lo) + __uint_as_float(hi);
}
__device__ __forceinline__ unsigned sw128(unsigned x) { return x ^ ((x >> 3) & 0x70u); }
__device__ __forceinline__ void cpa16(unsigned dst, const void* src) {
    asm volatile("cp.async.cg.shared.global [%0], [%1], 16;" :: "r"(dst), "l"(src));
}
__device__ __forceinline__ void ldm_x4(unsigned* r, unsigned addr) {
    asm volatile("ldmatrix.sync.aligned.m8n8.x4.shared.b16 {%0,%1,%2,%3}, [%4];"
                 : "=r"(r[0]), "=r"(r[1]), "=r"(r[2]), "=r"(r[3]) : "r"(addr));
}
__device__ __forceinline__ void mma16816(float* d, const unsigned* a,
                                         unsigned b0, unsigned b1) {
    asm volatile(
        "mma.sync.aligned.m16n8k16.row.col.f32.bf16.bf16.f32 "
        "{%0,%1,%2,%3}, {%4,%5,%6,%7}, {%8,%9}, {%0,%1,%2,%3};"
        : "+f"(d[0]), "+f"(d[1]), "+f"(d[2]), "+f"(d[3])
        : "r"(a[0]), "r"(a[1]), "r"(a[2]), "r"(a[3]), "r"(b0), "r"(b1));
}
// pack 2 fp32 -> bf16x2 (hi16 = a1, lo16 = a0)
__device__ __forceinline__ unsigned bf2(float a1, float a0) {
    unsigned d;
    asm("cvt.rn.bf16x2.f32 %0, %1, %2;" : "=r"(d) : "f"(a1), "f"(a0));
    return d;
}

// ---------------------------------------------------------------------------
// K1: node GEMM (fp32 FFMA2) — unchanged
// ---------------------------------------------------------------------------
extern "C" __global__ void __launch_bounds__(512, 1)
node_gemm_kernel(const float* __restrict__ x,
                 const float* __restrict__ Wsrc,
                 const float* __restrict__ Wtgt, int N)
{
    extern __shared__ float sm[];
    float4* a4 = reinterpret_cast<float4*>(sm);
    float4* w4 = reinterpret_cast<float4*>(sm + 16640);
    const float* Wm = blockIdx.y ? Wtgt : Wsrc;
    float* og = blockIdx.y ? g_xt : g_xs;

    const int t  = threadIdx.x;
    const int nb = blockIdx.x * 64;

#pragma unroll
    for (int r = 0; r < 8; r++) {
        int id = t + 512 * r;
        int row = id >> 6, c4 = id & 63;
        int n = nb + row;
        float4 v = make_float4(0.f, 0.f, 0.f, 0.f);
        if (n < N) v = __ldg(reinterpret_cast<const float4*>(x + (size_t)n * WDIM) + c4);
        a4[row * 65 + c4] = v;
    }

    const int et = t >> 5, jt = t & 31;
    unsigned sa = (unsigned)__cvta_generic_to_shared(sm);
    unsigned sw = sa + 16640u * 4u;

    u64 accp[4][8];
#pragma unroll
    for (int ee = 0; ee < 4; ee++)
#pragma unroll
        for (int jj = 0; jj < 8; jj++) accp[ee][jj] = 0ull;

#pragma unroll 1
    for (int kt = 0; kt < 8; kt++) {
        __syncthreads();
#pragma unroll
        for (int r = 0; r < 4; r++) {
            int id = t + 512 * r;
            int j = id >> 3, kq = id & 7;
            w4[j * 8 + (kq ^ ((j >> 3) & 7))] =
                __ldg(reinterpret_cast<const float4*>(Wm + (size_t)j * WDIM + kt * 32) + kq);
        }
        __syncthreads();
#pragma unroll
        for (int kq = 0; kq < 8; kq++) {
            u64 aL[4], aH[4];
#pragma unroll
            for (int ee = 0; ee < 4; ee++)
                lds_v2u64(aL[ee], aH[ee],
                          sa + (unsigned)(((et * 4 + ee) * 65 + kt * 8 + kq) * 16));
#pragma unroll
            for (int half = 0; half < 2; half++) {
                u64 bL[4], bH[4];
#pragma unroll
                for (int jj = 0; jj < 4; jj++)
                    lds_v2u64(bL[jj], bH[jj],
                              sw + (unsigned)(((jt * 8 + half * 4 + jj) * 8 + (kq ^ (jt & 7))) * 16));
#pragma unroll
                for (int ee = 0; ee < 4; ee++)
#pragma unroll
                    for (int jj = 0; jj < 4; jj++)
                        accp[ee][half * 4 + jj] =
                            ffma2(aH[ee], bH[jj], ffma2(aL[ee], bL[jj], accp[ee][half * 4 + jj]));
            }
        }
    }

#pragma unroll
    for (int ee = 0; ee < 4; ee++) {
        int n = nb + et * 4 + ee;
        if (n >= N) continue;
        float r0 = unpack_sum(accp[ee][0]), r1 = unpack_sum(accp[ee][1]);
        float r2 = unpack_sum(accp[ee][2]), r3 = unpack_sum(accp[ee][3]);
        float r4 = unpack_sum(accp[ee][4]), r5 = unpack_sum(accp[ee][5]);
        float r6 = unpack_sum(accp[ee][6]), r7 = unpack_sum(accp[ee][7]);
        float4* py = reinterpret_cast<float4*>(og + (size_t)n * WDIM + jt * 8);
        py[0] = make_float4(r0, r1, r2, r3);
        py[1] = make_float4(r4, r5, r6, r7);
    }
}

// ---------------------------------------------------------------------------
// Weight preprocessing (R5 layout): W_post hi/lo + Wg/Wv packed per-chunk
// ---------------------------------------------------------------------------
extern "C" __global__ void wsplit_kernel(const float* __restrict__ Wp,
                                         const float* __restrict__ Wg,
                                         const float* __restrict__ Wv)
{
    int i = blockIdx.x * blockDim.x + threadIdx.x;
    if (i < 65536) {
        float v = Wp[i];
        __nv_bfloat16 h = __float2bfloat16(v);
        float lof = v - __bfloat162float(h);
        __nv_bfloat16 l = __float2bfloat16(lof);
        g_wp_hi[i] = *reinterpret_cast<unsigned short*>(&h);
        g_wp_lo[i] = *reinterpret_cast<unsigned short*>(&l);
    }
    if (i < 16384) {
        int c   = i >> 12;
        int row = (i >> 6) & 63;
        int gv  = (i >> 5) & 1;
        int d   = i & 31;
        int h   = c * 2 + (row >> 5);
        int f   = row & 31;
        const float* Wm = gv ? Wv : Wg;
        float v = Wm[(size_t)h * 1024 + f * 32 + d];
        __nv_bfloat16 hh = __float2bfloat16(v);
        float lof = v - __bfloat162float(hh);
        __nv_bfloat16 ll = __float2bfloat16(lof);
        g_wgv_hi[i] = *reinterpret_cast<unsigned short*>(&hh);
        g_wgv_lo[i] = *reinterpret_cast<unsigned short*>(&ll);
    }
}

// ---------------------------------------------------------------------------
// K2 (fused), R9 = R5 arithmetic, 2 barriers/chunk (no chunk-end barrier).
// ACT/WGV/WP double-buffered; XN/GIN single (only read by P2, protected by S2).
// stage(c+1) issued AFTER S1(c): every warp past S1(c) has finished P3(c-1),
// so rewriting buffer (c+1)&1 is race-free.
// smem layout (bytes):
//  tgt@0(256) pad->1024
//  XNH@1024 XNL@9216 GINH@17408 GINL@25600               (8K each)
//  ACT buf0 @33792 (hi 8K + lo 8K) buf1 @50176           (16K each)
//  WGV buf0 @66560 (hi 8K + lo 8K) buf1 @82944           (16K each)
//  WP  buf0 @99328 (hi 32K + lo 32K) buf1 @164864        (64K each)
//  total 230400
// ---------------------------------------------------------------------------
#define XNH_O  1024u
#define XNL_O  9216u
#define GINH_O 17408u
#define GINL_O 25600u
#define ACT_O  33792u
#define ACTBUF 16384u
#define WGV_O  66560u
#define WGVBUF 16384u
#define WP_O   99328u
#define WPBUF  65536u

extern "C" __global__ void __launch_bounds__(512, 1)
fused_edge_kernel(const int* __restrict__ eidx, const int* __restrict__ eattr,
                  const float* __restrict__ emb, float* __restrict__ out, int E)
{
    extern __shared__ char smc[];
    unsigned sb = (unsigned)__cvta_generic_to_shared(smc);
    int* tgt_s = reinterpret_cast<int*>(smc);
    const int t = threadIdx.x, lane = t & 31, wid = t >> 5;
    const int eb = blockIdx.x * 64;

    if (t < 64) {
        int e = eb + t;
        tgt_s[t] = (e < E) ? __ldg(eidx + E + e) : -1;
    }

    const int wm = wid & 1, wn = wid >> 1;
    const int m0 = wm * 32, n0 = wn * 32;
    float acc[2][4][4];
#pragma unroll
    for (int mt = 0; mt < 2; mt++)
#pragma unroll
        for (int nn = 0; nn < 4; nn++)
#pragma unroll
            for (int q = 0; q < 4; q++) acc[mt][nn][q] = 0.f;

    const int e_l = t >> 3, sub = t & 7;
    const int e = eb + e_l;
    const int eg = wid >> 2, hl = (wid >> 1) & 1, nh = wid & 1;

    // ---- stage WP + WGV chunk cc into buffers cc&1 (one commit group) ----
    auto stage = [&](int cc) {
        unsigned wpb = sb + WP_O + (unsigned)(cc & 1) * WPBUF;
#pragma unroll
        for (int i = 0; i < 4; i++) {
            int u = t + 512 * i;
            int n = u >> 3, q = u & 7;
            unsigned off = sw128((unsigned)(n * 128 + q * 16));
            cpa16(wpb + off,          g_wp_hi + (size_t)n * 256 + cc * 64 + q * 8);
            cpa16(wpb + 32768u + off, g_wp_lo + (size_t)n * 256 + cc * 64 + q * 8);
        }
        {
            unsigned wgb = sb + WGV_O + (unsigned)(cc & 1) * WGVBUF;
            int r = t >> 3, q = t & 7;
            unsigned off = sw128((unsigned)(r * 128 + q * 16));
            cpa16(wgb + off,         g_wgv_hi + (size_t)(cc * 64 + r) * 64 + q * 8);
            cpa16(wgb + 8192u + off, g_wgv_lo + (size_t)(cc * 64 + r) * 64 + q * 8);
        }
        asm volatile("cp.async.commit_group;" ::: "memory");
    };

    stage(0);
    __syncthreads();   // tgt_s visible to all warps before P1 reads it

#pragma unroll 1
    for (int c = 0; c < 4; c++) {
        // ---- P1: xn/gin for this chunk's 2 heads (direct __ldg gathers) ----
        {
            unsigned soff = sw128((unsigned)(e_l * 128 + sub * 16));
            if (e < E) {
                int s  = __ldg(eidx + e);
                int tg = tgt_s[e_l];
                const float4* ps = reinterpret_cast<const float4*>(
                    g_xs + (size_t)s * WDIM + c * 64 + sub * 8);
                const float4* pt = reinterpret_cast<const float4*>(
                    g_xt + (size_t)tg * WDIM + c * 64 + sub * 8);
                float xx[8];
                float4 a0 = ps[0], a1 = ps[1], b0 = pt[0], b1 = pt[1];
                xx[0] = a0.x + b0.x; xx[1] = a0.y + b0.y; xx[2] = a0.z + b0.z; xx[3] = a0.w + b0.w;
                xx[4] = a1.x + b1.x; xx[5] = a1.y + b1.y; xx[6] = a1.z + b1.z; xx[7] = a1.w + b1.w;
                float sum = 0.f, sq = 0.f;
#pragma unroll
                for (int i = 0; i < 8; i++) { sum += xx[i]; sq += xx[i] * xx[i]; }
                sum += __shfl_xor_sync(0xFFFFFFFFu, sum, 1);
                sq  += __shfl_xor_sync(0xFFFFFFFFu, sq, 1);
                sum += __shfl_xor_sync(0xFFFFFFFFu, sum, 2);
                sq  += __shfl_xor_sync(0xFFFFFFFFu, sq, 2);
                float mu = sum * (1.f / 32.f);
                float var = sq * (1.f / 32.f) - mu * mu;
                float rstd = rsqrtf(var + 1e-5f);

                float bag[8];
#pragma unroll
                for (int i = 0; i < 8; i++) bag[i] = 0.f;
                float cnt = 0.f;
#pragma unroll
                for (int b = 0; b < 3; b++) {
                    int a = __ldg(eattr + (size_t)e * 3 + b);
                    if (a != 0) {
                        cnt += 1.f;
                        const float4* pe = reinterpret_cast<const float4*>(
                            emb + (size_t)a * WDIM + c * 64 + sub * 8);
                        float4 e0 = __ldg(pe), e1 = __ldg(pe + 1);
                        bag[0] += e0.x; bag[1] += e0.y; bag[2] += e0.z; bag[3] += e0.w;
                        bag[4] += e1.x; bag[5] += e1.y; bag[6] += e1.z; bag[7] += e1.w;
                    }
                }
                float inv = 1.f / fmaxf(cnt, 1.f);
                float xn[8], gn[8];
#pragma unroll
                for (int i = 0; i < 8; i++) {
                    xn[i] = (xx[i] - mu) * rstd;
                    gn[i] = xn[i] + bag[i] * inv;
                }
                unsigned xh[4], xl[4], gh[4], gl[4];
#pragma unroll
                for (int p = 0; p < 4; p++) {
                    unsigned hp = bf2(xn[2 * p + 1], xn[2 * p]);
                    float h0 = __uint_as_float(hp << 16);
                    float h1 = __uint_as_float(hp & 0xFFFF0000u);
                    xh[p] = hp;
                    xl[p] = bf2(xn[2 * p + 1] - h1, xn[2 * p] - h0);
                    hp = bf2(gn[2 * p + 1], gn[2 * p]);
                    h0 = __uint_as_float(hp << 16);
                    h1 = __uint_as_float(hp & 0xFFFF0000u);
                    gh[p] = hp;
                    gl[p] = bf2(gn[2 * p + 1] - h1, gn[2 * p] - h0);
                }
                asm volatile("st.shared.v4.b32 [%0], {%1,%2,%3,%4};" ::
                             "r"(sb + XNH_O + soff), "r"(xh[0]), "r"(xh[1]), "r"(xh[2]), "r"(xh[3]));
                asm volatile("st.shared.v4.b32 [%0], {%1,%2,%3,%4};" ::
                             "r"(sb + XNL_O + soff), "r"(xl[0]), "r"(xl[1]), "r"(xl[2]), "r"(xl[3]));
                asm volatile("st.shared.v4.b32 [%0], {%1,%2,%3,%4};" ::
                             "r"(sb + GINH_O + soff), "r"(gh[0]), "r"(gh[1]), "r"(gh[2]), "r"(gh[3]));
                asm volatile("st.shared.v4.b32 [%0], {%1,%2,%3,%4};" ::
                             "r"(sb + GINL_O + soff), "r"(gl[0]), "r"(gl[1]), "r"(gl[2]), "r"(gl[3]));
            } else {
                asm volatile("st.shared.v4.b32 [%0], {%1,%1,%1,%1};" :: "r"(sb + XNH_O + soff), "r"(0u));
                asm volatile("st.shared.v4.b32 [%0], {%1,%1,%1,%1};" :: "r"(sb + XNL_O + soff), "r"(0u));
                asm volatile("st.shared.v4.b32 [%0], {%1,%1,%1,%1};" :: "r"(sb + GINH_O + soff), "r"(0u));
                asm volatile("st.shared.v4.b32 [%0], {%1,%1,%1,%1};" :: "r"(sb + GINL_O + soff), "r"(0u));
            }
        }
        // wait for this chunk's staged weights (committed one chunk ago)
        asm volatile("cp.async.wait_group 0;" ::: "memory");
        __syncthreads();   // S1: xn/gin + WGV(c) + WP(c) visible to all

        // prefetch next chunk's weights (safe: all warps past P3(c-1))
        if (c < 3) stage(c + 1);

        // ---- P2: gate/val HMMA (3-split) from smem WGV buf ----
        {
            unsigned wgb = sb + WGV_O + (unsigned)(c & 1) * WGVBUF;
            unsigned acb = sb + ACT_O + (unsigned)(c & 1) * ACTBUF;
            unsigned agh[2][4], agl[2][4], axh[2][4], axl[2][4];
            unsigned arow = (unsigned)((eg * 16 + (lane & 15)) * 128 + hl * 64 + (lane >> 4) * 16);
#pragma unroll
            for (int ks = 0; ks < 2; ks++) {
                unsigned off = sw128(arow + ks * 32);
                ldm_x4(agh[ks], sb + GINH_O + off);
                ldm_x4(agl[ks], sb + GINL_O + off);
                ldm_x4(axh[ks], sb + XNH_O + off);
                ldm_x4(axl[ks], sb + XNL_O + off);
            }
            unsigned brow = (unsigned)((hl * 32 + nh * 16 + (lane & 7) + ((lane >> 4) & 1) * 8) * 128
                                       + ((lane >> 3) & 1) * 16);
            unsigned bgh[2][4], bgl[2][4], bvh[2][4], bvl[2][4];
#pragma unroll
            for (int ks = 0; ks < 2; ks++) {
                unsigned offg = sw128(brow + ks * 32);
                unsigned offv = sw128(brow + 64 + ks * 32);
                ldm_x4(bgh[ks], wgb + offg);
                ldm_x4(bgl[ks], wgb + 8192u + offg);
                ldm_x4(bvh[ks], wgb + offv);
                ldm_x4(bvl[ks], wgb + 8192u + offv);
            }
            float gacc[2][4], vacc[2][4];
#pragma unroll
            for (int j = 0; j < 2; j++)
#pragma unroll
                for (int q = 0; q < 4; q++) { gacc[j][q] = 0.f; vacc[j][q] = 0.f; }
#pragma unroll
            for (int ks = 0; ks < 2; ks++)
#pragma unroll
                for (int j = 0; j < 2; j++) {
                    mma16816(gacc[j], agh[ks], bgh[ks][2 * j], bgh[ks][2 * j + 1]);
                    mma16816(gacc[j], agh[ks], bgl[ks][2 * j], bgl[ks][2 * j + 1]);
                    mma16816(gacc[j], agl[ks], bgh[ks][2 * j], bgh[ks][2 * j + 1]);
                    mma16816(vacc[j], axh[ks], bvh[ks][2 * j], bvh[ks][2 * j + 1]);
                    mma16816(vacc[j], axh[ks], bvl[ks][2 * j], bvl[ks][2 * j + 1]);
                    mma16816(vacc[j], axl[ks], bvh[ks][2 * j], bvh[ks][2 * j + 1]);
                }
#pragma unroll
            for (int j = 0; j < 2; j++)
#pragma unroll
                for (int half = 0; half < 2; half++) {
                    float a0 = fmaxf(gacc[j][half * 2], 0.f) * vacc[j][half * 2];
                    float a1 = fmaxf(gacc[j][half * 2 + 1], 0.f) * vacc[j][half * 2 + 1];
                    int row = eg * 16 + (lane >> 2) + half * 8;
                    int col = hl * 32 + nh * 16 + j * 8 + (lane & 3) * 2;
                    unsigned off = sw128((unsigned)(row * 128 + col * 2));
                    unsigned hp = bf2(a1, a0);
                    float h0 = __uint_as_float(hp << 16);
                    float h1 = __uint_as_float(hp & 0xFFFF0000u);
                    unsigned lp = bf2(a1 - h1, a0 - h0);
                    asm volatile("st.shared.b32 [%0], %1;" :: "r"(acb + off), "r"(hp));
                    asm volatile("st.shared.b32 [%0], %1;" :: "r"(acb + 8192u + off), "r"(lp));
                }
        }
        __syncthreads();   // S2: act(c) visible

        // ---- P3: W_post chunk mainloop (no chunk-end barrier after this) ----
        {
            unsigned wpb = sb + WP_O + (unsigned)(c & 1) * WPBUF;
            unsigned acb = sb + ACT_O + (unsigned)(c & 1) * ACTBUF;
#pragma unroll
            for (int ks = 0; ks < 4; ks++) {
                unsigned ah[2][4], al[2][4];
#pragma unroll
                for (int mt = 0; mt < 2; mt++) {
                    unsigned off = sw128((unsigned)((m0 + mt * 16 + (lane & 15)) * 128
                                                    + ks * 32 + (lane >> 4) * 16));
                    ldm_x4(ah[mt], acb + off);
                    ldm_x4(al[mt], acb + 8192u + off);
                }
#pragma unroll
                for (int nt = 0; nt < 2; nt++) {
                    unsigned off = sw128((unsigned)((n0 + nt * 16 + (lane & 7)
                                                     + ((lane >> 4) & 1) * 8) * 128
                                                    + ks * 32 + ((lane >> 3) & 1) * 16));
                    unsigned bh[4], bl[4];
                    ldm_x4(bh, wpb + off);
                    ldm_x4(bl, wpb + 32768u + off);
#pragma unroll
                    for (int j = 0; j < 2; j++) {
                        int nn = nt * 2 + j;
#pragma unroll
                        for (int mt = 0; mt < 2; mt++) {
                            mma16816(acc[mt][nn], ah[mt], bh[2 * j], bh[2 * j + 1]);
                            mma16816(acc[mt][nn], ah[mt], bl[2 * j], bl[2 * j + 1]);
                            mma16816(acc[mt][nn], al[mt], bh[2 * j], bh[2 * j + 1]);
                        }
                    }
                }
            }
        }
        // no S3: fast warps proceed directly to P1(c+1)
    }

    // ---- epilogue: scatter ----
#pragma unroll
    for (int mt = 0; mt < 2; mt++) {
        int r0 = m0 + mt * 16 + (lane >> 2);
        int r1 = r0 + 8;
        int tg0 = tgt_s[r0], tg1 = tgt_s[r1];
        float* p0 = out + (size_t)(tg0 < 0 ? 0 : tg0) * WDIM;
        float* p1 = out + (size_t)(tg1 < 0 ? 0 : tg1) * WDIM;
#pragma unroll
        for (int nn = 0; nn < 4; nn++) {
            int col = n0 + nn * 8 + (lane & 3) * 2;
            if (tg0 >= 0)
                asm volatile("red.global.add.v2.f32 [%0], {%1,%2};" ::
                             "l"(p0 + col), "f"(acc[mt][nn][0]), "f"(acc[mt][nn][1]) : "memory");
            if (tg1 >= 0)
                asm volatile("red.global.add.v2.f32 [%0], {%1,%2};" ::
                             "l"(p1 + col), "f"(acc[mt][nn][2]), "f"(acc[mt][nn][3]) : "memory");
        }
    }
}

// ---------------------------------------------------------------------------
// K3: out[n,j] *= deg[n]^deg_param[j]
// ---------------------------------------------------------------------------
extern "C" __global__ void scale_kernel(float* __restrict__ out,
                                        const float* __restrict__ deg,
                                        const float* __restrict__ dp, int N)
{
    int idx = blockIdx.x * blockDim.x + threadIdx.x;
    if (idx < N * WDIM) {
        int n = idx >> 8, j = idx & 255;
        out[idx] *= __powf(__ldg(deg + n), __ldg(dp + j));
    }
}

// ---------------------------------------------------------------------------
extern "C" void kernel_launch(void* const* d_in, const int* in_sizes, int n_in,
                              void* d_out, int out_size)
{
    const float* x    = (const float*)d_in[0];
    const float* deg  = (const float*)d_in[1];
    const int*   eidx = (const int*)d_in[2];
    const int*   eattr= (const int*)d_in[3];
    const float* Wsrc = (const float*)d_in[4];
    const float* Wtgt = (const float*)d_in[5];
    const float* emb  = (const float*)d_in[6];
    const float* Wg   = (const float*)d_in[7];
    const float* Wv   = (const float*)d_in[8];
    const float* Wp   = (const float*)d_in[9];
    const float* dp   = (const float*)d_in[10];
    float* out = (float*)d_out;

    int N = in_sizes[0] / WDIM;
    int E = in_sizes[2] / 2;

    const int NODE_SMEM  = (16640 + 8192) * 4;      // 99328 B
    const int FUSED_SMEM = 230400;                  // see layout comment

    cudaFuncSetAttribute(node_gemm_kernel,
                         cudaFuncAttributeMaxDynamicSharedMemorySize, NODE_SMEM);
    cudaFuncSetAttribute(fused_edge_kernel,
                         cudaFuncAttributeMaxDynamicSharedMemorySize, FUSED_SMEM);

    cudaMemsetAsync(d_out, 0, (size_t)out_size * sizeof(float));

    wsplit_kernel<<<64, 1024>>>(Wp, Wg, Wv);
    dim3 ng((N + 63) / 64, 2);
    node_gemm_kernel<<<ng, 512, NODE_SMEM>>>(x, Wsrc, Wtgt, N);
    fused_edge_kernel<<<(E + 63) / 64, 512, FUSED_SMEM>>>(eidx, eattr, emb, out, E);
    scale_kernel<<<((size_t)N * WDIM + 511) / 512, 512>>>(out, deg, dp, N);
}

// round 10
// speedup vs baseline: 1.4648x; 1.0566x over previous
#include <cuda_runtime.h>
#include <cuda_bf16.h>
#include <cstdint>

#define WDIM 256

// ---------------------------------------------------------------------------
// Scratch (device globals)
// ---------------------------------------------------------------------------
__device__ float g_xs[2560000];              // [N,256]
__device__ float g_xt[2560000];
__device__ unsigned short g_x_hi[2560000];   // x bf16 hi/lo [N,256]
__device__ unsigned short g_x_lo[2560000];
__device__ unsigned short g_wp_hi[65536];    // W_post bf16 hi [n,k]
__device__ unsigned short g_wp_lo[65536];
__device__ unsigned short g_wsrc_hi[65536];  // W_src bf16 hi/lo [n,k]
__device__ unsigned short g_wsrc_lo[65536];
__device__ unsigned short g_wtgt_hi[65536];
__device__ unsigned short g_wtgt_lo[65536];
// packed gate/val weights per chunk: [c][row=hl*32+f][ Wg d0..31 | Wv d0..31 ]
__device__ unsigned short g_wgv_hi[16384];
__device__ unsigned short g_wgv_lo[16384];

typedef unsigned long long u64;

__device__ __forceinline__ unsigned sw128(unsigned x) { return x ^ ((x >> 3) & 0x70u); }
__device__ __forceinline__ void cpa16(unsigned dst, const void* src) {
    asm volatile("cp.async.cg.shared.global [%0], [%1], 16;" :: "r"(dst), "l"(src));
}
__device__ __forceinline__ void zfill16(unsigned dst) {
    asm volatile("st.shared.v4.b32 [%0], {%1,%1,%1,%1};" :: "r"(dst), "r"(0u));
}
__device__ __forceinline__ void ldm_x4(unsigned* r, unsigned addr) {
    asm volatile("ldmatrix.sync.aligned.m8n8.x4.shared.b16 {%0,%1,%2,%3}, [%4];"
                 : "=r"(r[0]), "=r"(r[1]), "=r"(r[2]), "=r"(r[3]) : "r"(addr));
}
__device__ __forceinline__ void mma16816(float* d, const unsigned* a,
                                         unsigned b0, unsigned b1) {
    asm volatile(
        "mma.sync.aligned.m16n8k16.row.col.f32.bf16.bf16.f32 "
        "{%0,%1,%2,%3}, {%4,%5,%6,%7}, {%8,%9}, {%0,%1,%2,%3};"
        : "+f"(d[0]), "+f"(d[1]), "+f"(d[2]), "+f"(d[3])
        : "r"(a[0]), "r"(a[1]), "r"(a[2]), "r"(a[3]), "r"(b0), "r"(b1));
}
// pack 2 fp32 -> bf16x2 (hi16 = a1, lo16 = a0)
__device__ __forceinline__ unsigned bf2(float a1, float a0) {
    unsigned d;
    asm("cvt.rn.bf16x2.f32 %0, %1, %2;" : "=r"(d) : "f"(a1), "f"(a0));
    return d;
}

// ---------------------------------------------------------------------------
// Split x into bf16 hi/lo
// ---------------------------------------------------------------------------
extern "C" __global__ void xsplit_kernel(const float* __restrict__ x, int total)
{
    int i = blockIdx.x * blockDim.x + threadIdx.x;
    if (i < total) {
        float v = x[i];
        __nv_bfloat16 h = __float2bfloat16(v);
        float lof = v - __bfloat162float(h);
        __nv_bfloat16 l = __float2bfloat16(lof);
        g_x_hi[i] = *reinterpret_cast<unsigned short*>(&h);
        g_x_lo[i] = *reinterpret_cast<unsigned short*>(&l);
    }
}

// ---------------------------------------------------------------------------
// Weight preprocessing: W_post/W_src/W_tgt hi/lo + Wg/Wv packed per-chunk
// ---------------------------------------------------------------------------
extern "C" __global__ void wsplit_kernel(const float* __restrict__ Wp,
                                         const float* __restrict__ Ws,
                                         const float* __restrict__ Wt,
                                         const float* __restrict__ Wg,
                                         const float* __restrict__ Wv)
{
    int i = blockIdx.x * blockDim.x + threadIdx.x;
    if (i < 65536) {
        {
            float v = Wp[i];
            __nv_bfloat16 h = __float2bfloat16(v);
            float lof = v - __bfloat162float(h);
            __nv_bfloat16 l = __float2bfloat16(lof);
            g_wp_hi[i] = *reinterpret_cast<unsigned short*>(&h);
            g_wp_lo[i] = *reinterpret_cast<unsigned short*>(&l);
        }
        {
            float v = Ws[i];
            __nv_bfloat16 h = __float2bfloat16(v);
            float lof = v - __bfloat162float(h);
            __nv_bfloat16 l = __float2bfloat16(lof);
            g_wsrc_hi[i] = *reinterpret_cast<unsigned short*>(&h);
            g_wsrc_lo[i] = *reinterpret_cast<unsigned short*>(&l);
        }
        {
            float v = Wt[i];
            __nv_bfloat16 h = __float2bfloat16(v);
            float lof = v - __bfloat162float(h);
            __nv_bfloat16 l = __float2bfloat16(lof);
            g_wtgt_hi[i] = *reinterpret_cast<unsigned short*>(&h);
            g_wtgt_lo[i] = *reinterpret_cast<unsigned short*>(&l);
        }
    }
    if (i < 16384) {
        int c   = i >> 12;
        int row = (i >> 6) & 63;
        int gv  = (i >> 5) & 1;
        int d   = i & 31;
        int h   = c * 2 + (row >> 5);
        int f   = row & 31;
        const float* Wm = gv ? Wv : Wg;
        float v = Wm[(size_t)h * 1024 + f * 32 + d];
        __nv_bfloat16 hh = __float2bfloat16(v);
        float lof = v - __bfloat162float(hh);
        __nv_bfloat16 ll = __float2bfloat16(lof);
        g_wgv_hi[i] = *reinterpret_cast<unsigned short*>(&hh);
        g_wgv_lo[i] = *reinterpret_cast<unsigned short*>(&ll);
    }
}

// ---------------------------------------------------------------------------
// K1 (new): HMMA node GEMM, 3-split bf16. Block = 128 nodes x 256 outs.
// blockIdx.y selects src/tgt. 512 thr = 16 warps (4m x 4n), warp tile 32x64.
// Validated R3 fragment mapping; single-buffered chunk staging.
// smem: A_hi@0(16K) A_lo@16384 | B_hi@32768(32K) B_lo@65536 -> 98304 B
// ---------------------------------------------------------------------------
extern "C" __global__ void __launch_bounds__(512, 1)
hmma_node_kernel(int N)
{
    extern __shared__ char smc[];
    unsigned sb = (unsigned)__cvta_generic_to_shared(smc);
    const unsigned A_HI = sb, A_LO = sb + 16384u, B_HI = sb + 32768u, B_LO = sb + 65536u;
    const int t = threadIdx.x, lane = t & 31, wid = t >> 5;
    const int wm = wid & 3, wn = wid >> 2;
    const int m0 = wm * 32, n0 = wn * 64;
    const int nb = blockIdx.x * 128;
    const unsigned short* Wh = blockIdx.y ? g_wtgt_hi : g_wsrc_hi;
    const unsigned short* Wl = blockIdx.y ? g_wtgt_lo : g_wsrc_lo;
    float* og = blockIdx.y ? g_xt : g_xs;

    float acc[2][8][4];
#pragma unroll
    for (int mt = 0; mt < 2; mt++)
#pragma unroll
        for (int nn = 0; nn < 8; nn++)
#pragma unroll
            for (int q = 0; q < 4; q++) acc[mt][nn][q] = 0.f;

#pragma unroll 1
    for (int c = 0; c < 4; c++) {
        __syncthreads();   // previous chunk's ldmatrix reads done
        // stage A (128 rows x 8 segs x 16B per array)
#pragma unroll
        for (int i = 0; i < 2; i++) {
            int u = t + 512 * i;
            int r = u >> 3, q = u & 7;
            unsigned off = sw128((unsigned)(r * 128 + q * 16));
            int row = nb + r;
            if (row < N) {
                cpa16(A_HI + off, g_x_hi + (size_t)row * 256 + c * 64 + q * 8);
                cpa16(A_LO + off, g_x_lo + (size_t)row * 256 + c * 64 + q * 8);
            } else {
                zfill16(A_HI + off);
                zfill16(A_LO + off);
            }
        }
        // stage B (256 rows x 8 segs x 16B per array)
#pragma unroll
        for (int i = 0; i < 4; i++) {
            int u = t + 512 * i;
            int n = u >> 3, q = u & 7;
            unsigned off = sw128((unsigned)(n * 128 + q * 16));
            cpa16(B_HI + off, Wh + (size_t)n * 256 + c * 64 + q * 8);
            cpa16(B_LO + off, Wl + (size_t)n * 256 + c * 64 + q * 8);
        }
        asm volatile("cp.async.commit_group;" ::: "memory");
        asm volatile("cp.async.wait_group 0;" ::: "memory");
        __syncthreads();

#pragma unroll
        for (int ks = 0; ks < 4; ks++) {
            unsigned ah[2][4], al[2][4];
#pragma unroll
            for (int mt = 0; mt < 2; mt++) {
                unsigned off = sw128((unsigned)((m0 + mt * 16 + (lane & 15)) * 128
                                                + ks * 32 + (lane >> 4) * 16));
                ldm_x4(ah[mt], A_HI + off);
                ldm_x4(al[mt], A_LO + off);
            }
#pragma unroll
            for (int nt = 0; nt < 4; nt++) {
                unsigned off = sw128((unsigned)((n0 + nt * 16 + (lane & 7)
                                                 + ((lane >> 4) & 1) * 8) * 128
                                                + ks * 32 + ((lane >> 3) & 1) * 16));
                unsigned bh[4], bl[4];
                ldm_x4(bh, B_HI + off);
                ldm_x4(bl, B_LO + off);
#pragma unroll
                for (int j = 0; j < 2; j++) {
                    int nn = nt * 2 + j;
#pragma unroll
                    for (int mt = 0; mt < 2; mt++) {
                        mma16816(acc[mt][nn], ah[mt], bh[2 * j], bh[2 * j + 1]);
                        mma16816(acc[mt][nn], ah[mt], bl[2 * j], bl[2 * j + 1]);
                        mma16816(acc[mt][nn], al[mt], bh[2 * j], bh[2 * j + 1]);
                    }
                }
            }
        }
    }

    // store fp32 results
#pragma unroll
    for (int mt = 0; mt < 2; mt++) {
        int r0 = nb + m0 + mt * 16 + (lane >> 2);
        int r1 = r0 + 8;
#pragma unroll
        for (int nn = 0; nn < 8; nn++) {
            int col = n0 + nn * 8 + (lane & 3) * 2;
            if (r0 < N) {
                og[(size_t)r0 * WDIM + col]     = acc[mt][nn][0];
                og[(size_t)r0 * WDIM + col + 1] = acc[mt][nn][1];
            }
            if (r1 < N) {
                og[(size_t)r1 * WDIM + col]     = acc[mt][nn][2];
                og[(size_t)r1 * WDIM + col + 1] = acc[mt][nn][3];
            }
        }
    }
}

// ---------------------------------------------------------------------------
// K2 (fused), R9 exact: 2 barriers/chunk, ACT/WGV/WP double-buffered.
// ---------------------------------------------------------------------------
#define XNH_O  1024u
#define XNL_O  9216u
#define GINH_O 17408u
#define GINL_O 25600u
#define ACT_O  33792u
#define ACTBUF 16384u
#define WGV_O  66560u
#define WGVBUF 16384u
#define WP_O   99328u
#define WPBUF  65536u

extern "C" __global__ void __launch_bounds__(512, 1)
fused_edge_kernel(const int* __restrict__ eidx, const int* __restrict__ eattr,
                  const float* __restrict__ emb, float* __restrict__ out, int E)
{
    extern __shared__ char smc[];
    unsigned sb = (unsigned)__cvta_generic_to_shared(smc);
    int* tgt_s = reinterpret_cast<int*>(smc);
    const int t = threadIdx.x, lane = t & 31, wid = t >> 5;
    const int eb = blockIdx.x * 64;

    if (t < 64) {
        int e = eb + t;
        tgt_s[t] = (e < E) ? __ldg(eidx + E + e) : -1;
    }

    const int wm = wid & 1, wn = wid >> 1;
    const int m0 = wm * 32, n0 = wn * 32;
    float acc[2][4][4];
#pragma unroll
    for (int mt = 0; mt < 2; mt++)
#pragma unroll
        for (int nn = 0; nn < 4; nn++)
#pragma unroll
            for (int q = 0; q < 4; q++) acc[mt][nn][q] = 0.f;

    const int e_l = t >> 3, sub = t & 7;
    const int e = eb + e_l;
    const int eg = wid >> 2, hl = (wid >> 1) & 1, nh = wid & 1;

    auto stage = [&](int cc) {
        unsigned wpb = sb + WP_O + (unsigned)(cc & 1) * WPBUF;
#pragma unroll
        for (int i = 0; i < 4; i++) {
            int u = t + 512 * i;
            int n = u >> 3, q = u & 7;
            unsigned off = sw128((unsigned)(n * 128 + q * 16));
            cpa16(wpb + off,          g_wp_hi + (size_t)n * 256 + cc * 64 + q * 8);
            cpa16(wpb + 32768u + off, g_wp_lo + (size_t)n * 256 + cc * 64 + q * 8);
        }
        {
            unsigned wgb = sb + WGV_O + (unsigned)(cc & 1) * WGVBUF;
            int r = t >> 3, q = t & 7;
            unsigned off = sw128((unsigned)(r * 128 + q * 16));
            cpa16(wgb + off,         g_wgv_hi + (size_t)(cc * 64 + r) * 64 + q * 8);
            cpa16(wgb + 8192u + off, g_wgv_lo + (size_t)(cc * 64 + r) * 64 + q * 8);
        }
        asm volatile("cp.async.commit_group;" ::: "memory");
    };

    stage(0);
    __syncthreads();

#pragma unroll 1
    for (int c = 0; c < 4; c++) {
        // ---- P1 ----
        {
            unsigned soff = sw128((unsigned)(e_l * 128 + sub * 16));
            if (e < E) {
                int s  = __ldg(eidx + e);
                int tg = tgt_s[e_l];
                const float4* ps = reinterpret_cast<const float4*>(
                    g_xs + (size_t)s * WDIM + c * 64 + sub * 8);
                const float4* pt = reinterpret_cast<const float4*>(
                    g_xt + (size_t)tg * WDIM + c * 64 + sub * 8);
                float xx[8];
                float4 a0 = ps[0], a1 = ps[1], b0 = pt[0], b1 = pt[1];
                xx[0] = a0.x + b0.x; xx[1] = a0.y + b0.y; xx[2] = a0.z + b0.z; xx[3] = a0.w + b0.w;
                xx[4] = a1.x + b1.x; xx[5] = a1.y + b1.y; xx[6] = a1.z + b1.z; xx[7] = a1.w + b1.w;
                float sum = 0.f, sq = 0.f;
#pragma unroll
                for (int i = 0; i < 8; i++) { sum += xx[i]; sq += xx[i] * xx[i]; }
                sum += __shfl_xor_sync(0xFFFFFFFFu, sum, 1);
                sq  += __shfl_xor_sync(0xFFFFFFFFu, sq, 1);
                sum += __shfl_xor_sync(0xFFFFFFFFu, sum, 2);
                sq  += __shfl_xor_sync(0xFFFFFFFFu, sq, 2);
                float mu = sum * (1.f / 32.f);
                float var = sq * (1.f / 32.f) - mu * mu;
                float rstd = rsqrtf(var + 1e-5f);

                float bag[8];
#pragma unroll
                for (int i = 0; i < 8; i++) bag[i] = 0.f;
                float cnt = 0.f;
#pragma unroll
                for (int b = 0; b < 3; b++) {
                    int a = __ldg(eattr + (size_t)e * 3 + b);
                    if (a != 0) {
                        cnt += 1.f;
                        const float4* pe = reinterpret_cast<const float4*>(
                            emb + (size_t)a * WDIM + c * 64 + sub * 8);
                        float4 e0 = __ldg(pe), e1 = __ldg(pe + 1);
                        bag[0] += e0.x; bag[1] += e0.y; bag[2] += e0.z; bag[3] += e0.w;
                        bag[4] += e1.x; bag[5] += e1.y; bag[6] += e1.z; bag[7] += e1.w;
                    }
                }
                float inv = 1.f / fmaxf(cnt, 1.f);
                float xn[8], gn[8];
#pragma unroll
                for (int i = 0; i < 8; i++) {
                    xn[i] = (xx[i] - mu) * rstd;
                    gn[i] = xn[i] + bag[i] * inv;
                }
                unsigned xh[4], xl[4], gh[4], gl[4];
#pragma unroll
                for (int p = 0; p < 4; p++) {
                    unsigned hp = bf2(xn[2 * p + 1], xn[2 * p]);
                    float h0 = __uint_as_float(hp << 16);
                    float h1 = __uint_as_float(hp & 0xFFFF0000u);
                    xh[p] = hp;
                    xl[p] = bf2(xn[2 * p + 1] - h1, xn[2 * p] - h0);
                    hp = bf2(gn[2 * p + 1], gn[2 * p]);
                    h0 = __uint_as_float(hp << 16);
                    h1 = __uint_as_float(hp & 0xFFFF0000u);
                    gh[p] = hp;
                    gl[p] = bf2(gn[2 * p + 1] - h1, gn[2 * p] - h0);
                }
                asm volatile("st.shared.v4.b32 [%0], {%1,%2,%3,%4};" ::
                             "r"(sb + XNH_O + soff), "r"(xh[0]), "r"(xh[1]), "r"(xh[2]), "r"(xh[3]));
                asm volatile("st.shared.v4.b32 [%0], {%1,%2,%3,%4};" ::
                             "r"(sb + XNL_O + soff), "r"(xl[0]), "r"(xl[1]), "r"(xl[2]), "r"(xl[3]));
                asm volatile("st.shared.v4.b32 [%0], {%1,%2,%3,%4};" ::
                             "r"(sb + GINH_O + soff), "r"(gh[0]), "r"(gh[1]), "r"(gh[2]), "r"(gh[3]));
                asm volatile("st.shared.v4.b32 [%0], {%1,%2,%3,%4};" ::
                             "r"(sb + GINL_O + soff), "r"(gl[0]), "r"(gl[1]), "r"(gl[2]), "r"(gl[3]));
            } else {
                asm volatile("st.shared.v4.b32 [%0], {%1,%1,%1,%1};" :: "r"(sb + XNH_O + soff), "r"(0u));
                asm volatile("st.shared.v4.b32 [%0], {%1,%1,%1,%1};" :: "r"(sb + XNL_O + soff), "r"(0u));
                asm volatile("st.shared.v4.b32 [%0], {%1,%1,%1,%1};" :: "r"(sb + GINH_O + soff), "r"(0u));
                asm volatile("st.shared.v4.b32 [%0], {%1,%1,%1,%1};" :: "r"(sb + GINL_O + soff), "r"(0u));
            }
        }
        asm volatile("cp.async.wait_group 0;" ::: "memory");
        __syncthreads();   // S1

        if (c < 3) stage(c + 1);

        // ---- P2 ----
        {
            unsigned wgb = sb + WGV_O + (unsigned)(c & 1) * WGVBUF;
            unsigned acb = sb + ACT_O + (unsigned)(c & 1) * ACTBUF;
            unsigned agh[2][4], agl[2][4], axh[2][4], axl[2][4];
            unsigned arow = (unsigned)((eg * 16 + (lane & 15)) * 128 + hl * 64 + (lane >> 4) * 16);
#pragma unroll
            for (int ks = 0; ks < 2; ks++) {
                unsigned off = sw128(arow + ks * 32);
                ldm_x4(agh[ks], sb + GINH_O + off);
                ldm_x4(agl[ks], sb + GINL_O + off);
                ldm_x4(axh[ks], sb + XNH_O + off);
                ldm_x4(axl[ks], sb + XNL_O + off);
            }
            unsigned brow = (unsigned)((hl * 32 + nh * 16 + (lane & 7) + ((lane >> 4) & 1) * 8) * 128
                                       + ((lane >> 3) & 1) * 16);
            unsigned bgh[2][4], bgl[2][4], bvh[2][4], bvl[2][4];
#pragma unroll
            for (int ks = 0; ks < 2; ks++) {
                unsigned offg = sw128(brow + ks * 32);
                unsigned offv = sw128(brow + 64 + ks * 32);
                ldm_x4(bgh[ks], wgb + offg);
                ldm_x4(bgl[ks], wgb + 8192u + offg);
                ldm_x4(bvh[ks], wgb + offv);
                ldm_x4(bvl[ks], wgb + 8192u + offv);
            }
            float gacc[2][4], vacc[2][4];
#pragma unroll
            for (int j = 0; j < 2; j++)
#pragma unroll
                for (int q = 0; q < 4; q++) { gacc[j][q] = 0.f; vacc[j][q] = 0.f; }
#pragma unroll
            for (int ks = 0; ks < 2; ks++)
#pragma unroll
                for (int j = 0; j < 2; j++) {
                    mma16816(gacc[j], agh[ks], bgh[ks][2 * j], bgh[ks][2 * j + 1]);
                    mma16816(gacc[j], agh[ks], bgl[ks][2 * j], bgl[ks][2 * j + 1]);
                    mma16816(gacc[j], agl[ks], bgh[ks][2 * j], bgh[ks][2 * j + 1]);
                    mma16816(vacc[j], axh[ks], bvh[ks][2 * j], bvh[ks][2 * j + 1]);
                    mma16816(vacc[j], axh[ks], bvl[ks][2 * j], bvl[ks][2 * j + 1]);
                    mma16816(vacc[j], axl[ks], bvh[ks][2 * j], bvh[ks][2 * j + 1]);
                }
#pragma unroll
            for (int j = 0; j < 2; j++)
#pragma unroll
                for (int half = 0; half < 2; half++) {
                    float a0 = fmaxf(gacc[j][half * 2], 0.f) * vacc[j][half * 2];
                    float a1 = fmaxf(gacc[j][half * 2 + 1], 0.f) * vacc[j][half * 2 + 1];
                    int row = eg * 16 + (lane >> 2) + half * 8;
                    int col = hl * 32 + nh * 16 + j * 8 + (lane & 3) * 2;
                    unsigned off = sw128((unsigned)(row * 128 + col * 2));
                    unsigned hp = bf2(a1, a0);
                    float h0 = __uint_as_float(hp << 16);
                    float h1 = __uint_as_float(hp & 0xFFFF0000u);
                    unsigned lp = bf2(a1 - h1, a0 - h0);
                    asm volatile("st.shared.b32 [%0], %1;" :: "r"(acb + off), "r"(hp));
                    asm volatile("st.shared.b32 [%0], %1;" :: "r"(acb + 8192u + off), "r"(lp));
                }
        }
        __syncthreads();   // S2

        // ---- P3 ----
        {
            unsigned wpb = sb + WP_O + (unsigned)(c & 1) * WPBUF;
            unsigned acb = sb + ACT_O + (unsigned)(c & 1) * ACTBUF;
#pragma unroll
            for (int ks = 0; ks < 4; ks++) {
                unsigned ah[2][4], al[2][4];
#pragma unroll
                for (int mt = 0; mt < 2; mt++) {
                    unsigned off = sw128((unsigned)((m0 + mt * 16 + (lane & 15)) * 128
                                                    + ks * 32 + (lane >> 4) * 16));
                    ldm_x4(ah[mt], acb + off);
                    ldm_x4(al[mt], acb + 8192u + off);
                }
#pragma unroll
                for (int nt = 0; nt < 2; nt++) {
                    unsigned off = sw128((unsigned)((n0 + nt * 16 + (lane & 7)
                                                     + ((lane >> 4) & 1) * 8) * 128
                                                    + ks * 32 + ((lane >> 3) & 1) * 16));
                    unsigned bh[4], bl[4];
                    ldm_x4(bh, wpb + off);
                    ldm_x4(bl, wpb + 32768u + off);
#pragma unroll
                    for (int j = 0; j < 2; j++) {
                        int nn = nt * 2 + j;
#pragma unroll
                        for (int mt = 0; mt < 2; mt++) {
                            mma16816(acc[mt][nn], ah[mt], bh[2 * j], bh[2 * j + 1]);
                            mma16816(acc[mt][nn], ah[mt], bl[2 * j], bl[2 * j + 1]);
                            mma16816(acc[mt][nn], al[mt], bh[2 * j], bh[2 * j + 1]);
                        }
                    }
                }
            }
        }
        // no chunk-end barrier
    }

    // ---- epilogue: scatter ----
#pragma unroll
    for (int mt = 0; mt < 2; mt++) {
        int r0 = m0 + mt * 16 + (lane >> 2);
        int r1 = r0 + 8;
        int tg0 = tgt_s[r0], tg1 = tgt_s[r1];
        float* p0 = out + (size_t)(tg0 < 0 ? 0 : tg0) * WDIM;
        float* p1 = out + (size_t)(tg1 < 0 ? 0 : tg1) * WDIM;
#pragma unroll
        for (int nn = 0; nn < 4; nn++) {
            int col = n0 + nn * 8 + (lane & 3) * 2;
            if (tg0 >= 0)
                asm volatile("red.global.add.v2.f32 [%0], {%1,%2};" ::
                             "l"(p0 + col), "f"(acc[mt][nn][0]), "f"(acc[mt][nn][1]) : "memory");
            if (tg1 >= 0)
                asm volatile("red.global.add.v2.f32 [%0], {%1,%2};" ::
                             "l"(p1 + col), "f"(acc[mt][nn][2]), "f"(acc[mt][nn][3]) : "memory");
        }
    }
}

// ---------------------------------------------------------------------------
// K3: out[n,j] *= deg[n]^deg_param[j]
// ---------------------------------------------------------------------------
extern "C" __global__ void scale_kernel(float* __restrict__ out,
                                        const float* __restrict__ deg,
                                        const float* __restrict__ dp, int N)
{
    int idx = blockIdx.x * blockDim.x + threadIdx.x;
    if (idx < N * WDIM) {
        int n = idx >> 8, j = idx & 255;
        out[idx] *= __powf(__ldg(deg + n), __ldg(dp + j));
    }
}

// ---------------------------------------------------------------------------
extern "C" void kernel_launch(void* const* d_in, const int* in_sizes, int n_in,
                              void* d_out, int out_size)
{
    const float* x    = (const float*)d_in[0];
    const float* deg  = (const float*)d_in[1];
    const int*   eidx = (const int*)d_in[2];
    const int*   eattr= (const int*)d_in[3];
    const float* Wsrc = (const float*)d_in[4];
    const float* Wtgt = (const float*)d_in[5];
    const float* emb  = (const float*)d_in[6];
    const float* Wg   = (const float*)d_in[7];
    const float* Wv   = (const float*)d_in[8];
    const float* Wp   = (const float*)d_in[9];
    const float* dp   = (const float*)d_in[10];
    float* out = (float*)d_out;

    int N = in_sizes[0] / WDIM;
    int E = in_sizes[2] / 2;
    int xtotal = in_sizes[0];

    const int NODE_SMEM  = 98304;
    const int FUSED_SMEM = 230400;

    cudaFuncSetAttribute(hmma_node_kernel,
                         cudaFuncAttributeMaxDynamicSharedMemorySize, NODE_SMEM);
    cudaFuncSetAttribute(fused_edge_kernel,
                         cudaFuncAttributeMaxDynamicSharedMemorySize, FUSED_SMEM);

    cudaMemsetAsync(d_out, 0, (size_t)out_size * sizeof(float));

    xsplit_kernel<<<(xtotal + 511) / 512, 512>>>(x, xtotal);
    wsplit_kernel<<<64, 1024>>>(Wp, Wsrc, Wtgt, Wg, Wv);
    dim3 ng((N + 127) / 128, 2);
    hmma_node_kernel<<<ng, 512, NODE_SMEM>>>(N);
    fused_edge_kernel<<<(E + 63) / 64, 512, FUSED_SMEM>>>(eidx, eattr, emb, out, E);
    scale_kernel<<<((size_t)N * WDIM + 511) / 512, 512>>>(out, deg, dp, N);
}